// round 1
// baseline (speedup 1.0000x reference)
#include <cuda_runtime.h>

#define D_MODEL 1024
#define NHEADS  16
#define DHEAD   64
#define BATCH   2
#define SEQ     2048
#define BT      (BATCH * SEQ)

// Scratch (allocation-free rule: __device__ globals)
__device__ float g_Q[BT * D_MODEL];
__device__ float g_K[BT * D_MODEL];
__device__ float g_V[BT * D_MODEL];
__device__ float g_ctx[BT * D_MODEL];

// ---------------------------------------------------------------------------
// SGEMM: C[M,N] = A[M,K] * B[K,N] (+ optional bias), all row-major, fp32.
// 128x128 CTA tile, BK=16, 256 threads, 8x8 per-thread microtile.
// M,N,K are compile-known multiples of the tile here (4096/1024/1024).
// ---------------------------------------------------------------------------
#define BM 128
#define BN 128
#define BK 16

__global__ __launch_bounds__(256)
void sgemm_bias_kernel(const float* __restrict__ A, const float* __restrict__ B,
                       const float* __restrict__ bias, float* __restrict__ C,
                       int M, int N, int K)
{
    __shared__ float As[BK][BM + 4];   // A tile transposed: As[k][m]
    __shared__ float Bs[BK][BN];       // Bs[k][n]

    const int tid  = threadIdx.x;
    const int tx   = tid & 15;         // 0..15 -> N microtile
    const int ty   = tid >> 4;         // 0..15 -> M microtile
    const int row0 = blockIdx.y * BM;
    const int col0 = blockIdx.x * BN;

    // global-load mapping
    const int aRow = tid >> 2;          // 0..63
    const int aCol = (tid & 3) << 2;    // 0,4,8,12
    const int bRow = tid >> 5;          // 0..7
    const int bCol = (tid & 31) << 2;   // 0..124

    float acc[8][8];
#pragma unroll
    for (int i = 0; i < 8; i++)
#pragma unroll
        for (int j = 0; j < 8; j++) acc[i][j] = 0.f;

    for (int k0 = 0; k0 < K; k0 += BK) {
        // Load A tile (128x16), store transposed
#pragma unroll
        for (int p = 0; p < 2; p++) {
            int r = aRow + p * 64;
            float4 v = *(const float4*)(A + (row0 + r) * K + k0 + aCol);
            As[aCol + 0][r] = v.x;
            As[aCol + 1][r] = v.y;
            As[aCol + 2][r] = v.z;
            As[aCol + 3][r] = v.w;
        }
        // Load B tile (16x128)
#pragma unroll
        for (int p = 0; p < 2; p++) {
            int r = bRow + p * 8;
            *(float4*)&Bs[r][bCol] = *(const float4*)(B + (k0 + r) * N + col0 + bCol);
        }
        __syncthreads();

#pragma unroll
        for (int kk = 0; kk < BK; kk++) {
            float ra[8], rb[8];
            *(float4*)&ra[0] = *(const float4*)&As[kk][ty * 8];
            *(float4*)&ra[4] = *(const float4*)&As[kk][ty * 8 + 4];
            *(float4*)&rb[0] = *(const float4*)&Bs[kk][tx * 8];
            *(float4*)&rb[4] = *(const float4*)&Bs[kk][tx * 8 + 4];
#pragma unroll
            for (int i = 0; i < 8; i++)
#pragma unroll
                for (int j = 0; j < 8; j++)
                    acc[i][j] = fmaf(ra[i], rb[j], acc[i][j]);
        }
        __syncthreads();
    }

#pragma unroll
    for (int i = 0; i < 8; i++) {
        int row = row0 + ty * 8 + i;
#pragma unroll
        for (int j = 0; j < 8; j += 4) {
            int col = col0 + tx * 8 + j;
            float4 v = make_float4(acc[i][j], acc[i][j + 1], acc[i][j + 2], acc[i][j + 3]);
            if (bias) {
                v.x += bias[col];
                v.y += bias[col + 1];
                v.z += bias[col + 2];
                v.w += bias[col + 3];
            }
            *(float4*)&C[row * N + col] = v;
        }
    }
}

// ---------------------------------------------------------------------------
// Causal flash attention, fp32, online softmax.
// One CTA per (batch, head, 64-row q tile). 256 threads = 16x16 layout,
// each thread owns a 4x4 microtile of S / O.
// Q,K,V,ctx layout: [BT, D_MODEL] row-major, head h occupies cols [h*64, h*64+64).
// ---------------------------------------------------------------------------
#define SSTR 68    // padded smem row stride (floats), multiple of 4 for float4

__global__ __launch_bounds__(256)
void attn_kernel(const float* __restrict__ Q, const float* __restrict__ K,
                 const float* __restrict__ V, float* __restrict__ ctx)
{
    extern __shared__ float smem[];
    float* Qt = smem;                  // [64][SSTR] : Qt[d][r]   (q transposed, pre-scaled)
    float* Kt = Qt + 64 * SSTR;        // [64][SSTR] : Kt[d][c]   (k transposed)
    float* Vs = Kt + 64 * SSTR;        // [64][SSTR] : Vs[k][d]
    float* Pt = Vs + 64 * SSTR;        // [64][SSTR] : Pt[k][r]   (P transposed)

    const int tid = threadIdx.x;
    const int tx  = tid & 15;          // owns d/S columns c0..c0+3
    const int ty  = tid >> 4;          // owns q rows r0..r0+3
    const int qt  = gridDim.x - 1 - blockIdx.x;   // heavy tiles first (wave balance)
    const int h   = blockIdx.y;
    const int b   = blockIdx.z;
    const int r0  = ty * 4, c0 = tx * 4;

    const int base = (b * SEQ) * D_MODEL + h * DHEAD;
    const float* Qg = Q + base + qt * 64 * D_MODEL;

    // Load Q tile, transpose, pre-scale by 1/sqrt(64)
    for (int i = tid; i < 64 * 16; i += 256) {
        int r = i >> 4, c4 = (i & 15) << 2;
        float4 v = *(const float4*)(Qg + r * D_MODEL + c4);
        Qt[(c4 + 0) * SSTR + r] = v.x * 0.125f;
        Qt[(c4 + 1) * SSTR + r] = v.y * 0.125f;
        Qt[(c4 + 2) * SSTR + r] = v.z * 0.125f;
        Qt[(c4 + 3) * SSTR + r] = v.w * 0.125f;
    }

    float m[4], l[4], o[4][4];
#pragma unroll
    for (int i = 0; i < 4; i++) {
        m[i] = -1e30f; l[i] = 0.f;
#pragma unroll
        for (int j = 0; j < 4; j++) o[i][j] = 0.f;
    }

    for (int kt = 0; kt <= qt; kt++) {
        __syncthreads();   // previous iteration's smem reads done (also covers Q load)
        const float* Kg = K + base + kt * 64 * D_MODEL;
        const float* Vg = V + base + kt * 64 * D_MODEL;
        for (int i = tid; i < 64 * 16; i += 256) {
            int r = i >> 4, c4 = (i & 15) << 2;
            float4 kv = *(const float4*)(Kg + r * D_MODEL + c4);
            Kt[(c4 + 0) * SSTR + r] = kv.x;
            Kt[(c4 + 1) * SSTR + r] = kv.y;
            Kt[(c4 + 2) * SSTR + r] = kv.z;
            Kt[(c4 + 3) * SSTR + r] = kv.w;
            *(float4*)&Vs[r * SSTR + c4] = *(const float4*)(Vg + r * D_MODEL + c4);
        }
        __syncthreads();

        // S = (Q/sqrt(d)) K^T  : 4x4 microtile
        float s[4][4];
#pragma unroll
        for (int i = 0; i < 4; i++)
#pragma unroll
            for (int j = 0; j < 4; j++) s[i][j] = 0.f;

        for (int kk = 0; kk < 64; kk++) {
            float qa[4], kb[4];
            *(float4*)qa = *(const float4*)&Qt[kk * SSTR + r0];
            *(float4*)kb = *(const float4*)&Kt[kk * SSTR + c0];
#pragma unroll
            for (int i = 0; i < 4; i++)
#pragma unroll
                for (int j = 0; j < 4; j++)
                    s[i][j] = fmaf(qa[i], kb[j], s[i][j]);
        }

        // causal mask on the diagonal tile
        if (kt == qt) {
#pragma unroll
            for (int i = 0; i < 4; i++)
#pragma unroll
                for (int j = 0; j < 4; j++)
                    if (c0 + j > r0 + i) s[i][j] = -1e30f;
        }

        // online softmax per row, reduce across the 16 tx lanes (half-warp groups)
#pragma unroll
        for (int i = 0; i < 4; i++) {
            float mn = fmaxf(fmaxf(s[i][0], s[i][1]), fmaxf(s[i][2], s[i][3]));
            mn = fmaxf(mn, __shfl_xor_sync(0xffffffffu, mn, 1, 16));
            mn = fmaxf(mn, __shfl_xor_sync(0xffffffffu, mn, 2, 16));
            mn = fmaxf(mn, __shfl_xor_sync(0xffffffffu, mn, 4, 16));
            mn = fmaxf(mn, __shfl_xor_sync(0xffffffffu, mn, 8, 16));
            float mnew = fmaxf(m[i], mn);
            float scl  = __expf(m[i] - mnew);
            float ls = 0.f;
#pragma unroll
            for (int j = 0; j < 4; j++) {
                float p = __expf(s[i][j] - mnew);
                s[i][j] = p;
                ls += p;
            }
            ls += __shfl_xor_sync(0xffffffffu, ls, 1, 16);
            ls += __shfl_xor_sync(0xffffffffu, ls, 2, 16);
            ls += __shfl_xor_sync(0xffffffffu, ls, 4, 16);
            ls += __shfl_xor_sync(0xffffffffu, ls, 8, 16);
            l[i] = l[i] * scl + ls;
            m[i] = mnew;
#pragma unroll
            for (int j = 0; j < 4; j++) o[i][j] *= scl;
            // stash P transposed: Pt[k][r]
#pragma unroll
            for (int j = 0; j < 4; j++)
                Pt[(c0 + j) * SSTR + (r0 + i)] = s[i][j];
        }
        __syncthreads();

        // O += P * V
        for (int kk = 0; kk < 64; kk++) {
            float pa[4], vb[4];
            *(float4*)pa = *(const float4*)&Pt[kk * SSTR + r0];
            *(float4*)vb = *(const float4*)&Vs[kk * SSTR + c0];
#pragma unroll
            for (int i = 0; i < 4; i++)
#pragma unroll
                for (int j = 0; j < 4; j++)
                    o[i][j] = fmaf(pa[i], vb[j], o[i][j]);
        }
    }

    // finalize: divide by row sums, write ctx
    float* Cg = ctx + base + qt * 64 * D_MODEL;
#pragma unroll
    for (int i = 0; i < 4; i++) {
        float inv = 1.f / l[i];
        float4 v = make_float4(o[i][0] * inv, o[i][1] * inv, o[i][2] * inv, o[i][3] * inv);
        *(float4*)(Cg + (r0 + i) * D_MODEL + c0) = v;
    }
}

// ---------------------------------------------------------------------------
extern "C" void kernel_launch(void* const* d_in, const int* in_sizes, int n_in,
                              void* d_out, int out_size)
{
    const float* x  = (const float*)d_in[0];
    const float* Wq = (const float*)d_in[1];
    const float* Wk = (const float*)d_in[2];
    const float* Wv = (const float*)d_in[3];
    const float* Wo = (const float*)d_in[4];
    const float* bo = (const float*)d_in[5];
    float* out = (float*)d_out;

    float *Qb, *Kb, *Vb, *Cb;
    cudaGetSymbolAddress((void**)&Qb, g_Q);
    cudaGetSymbolAddress((void**)&Kb, g_K);
    cudaGetSymbolAddress((void**)&Vb, g_V);
    cudaGetSymbolAddress((void**)&Cb, g_ctx);

    const size_t asmem = (size_t)4 * 64 * SSTR * sizeof(float);   // 69632 B
    cudaFuncSetAttribute(attn_kernel, cudaFuncAttributeMaxDynamicSharedMemorySize,
                         (int)asmem);

    dim3 gblock(256);
    dim3 ggrid(D_MODEL / BN, BT / BM);   // (8, 32)

    sgemm_bias_kernel<<<ggrid, gblock>>>(x, Wq, nullptr, Qb, BT, D_MODEL, D_MODEL);
    sgemm_bias_kernel<<<ggrid, gblock>>>(x, Wk, nullptr, Kb, BT, D_MODEL, D_MODEL);
    sgemm_bias_kernel<<<ggrid, gblock>>>(x, Wv, nullptr, Vb, BT, D_MODEL, D_MODEL);

    dim3 agrid(SEQ / 64, NHEADS, BATCH);  // (32, 16, 2)
    attn_kernel<<<agrid, 256, asmem>>>(Qb, Kb, Vb, Cb);

    sgemm_bias_kernel<<<ggrid, gblock>>>(Cb, Wo, bo, out, BT, D_MODEL, D_MODEL);
}

// round 2
// speedup vs baseline: 1.8560x; 1.8560x over previous
#include <cuda_runtime.h>
#include <cstdint>

#define D_MODEL 1024
#define NHEADS  16
#define DHEAD   64
#define BATCH   2
#define SEQ     2048
#define BT      (BATCH * SEQ)

// Scratch (allocation-free rule: __device__ globals)
__device__ float g_Q[BT * D_MODEL];
__device__ float g_K[BT * D_MODEL];
__device__ float g_V[BT * D_MODEL];
__device__ float g_ctx[BT * D_MODEL];

__device__ __forceinline__ uint32_t f2tf(float f) {
    uint32_t u;
    asm("cvt.rna.tf32.f32 %0, %1;" : "=r"(u) : "f"(f));
    return u;
}

__device__ __forceinline__ void mma_tf32(float* c, const uint32_t* a, const uint32_t* b) {
    asm volatile(
        "mma.sync.aligned.m16n8k8.row.col.f32.tf32.tf32.f32 "
        "{%0,%1,%2,%3},{%4,%5,%6,%7},{%8,%9},{%0,%1,%2,%3};"
        : "+f"(c[0]), "+f"(c[1]), "+f"(c[2]), "+f"(c[3])
        : "r"(a[0]), "r"(a[1]), "r"(a[2]), "r"(a[3]), "r"(b[0]), "r"(b[1]));
}

// ---------------------------------------------------------------------------
// tf32 GEMM: C[M,N] = A[M,K] @ B[K,N] (+bias). 128x128 CTA tile, BK=32,
// 256 threads = 8 warps as 4(m)x2(n), warp tile 32x64. Double-buffered smem.
// Smem strides chosen for conflict-free fragment LDS:
//   A stride 36 (mod32=4): bank = 4*(lane>>2) + (lane&3)  -> 32 distinct
//   B stride 136 (mod32=8): bank = 8*(lane&3) + (lane>>2) -> 32 distinct
// ---------------------------------------------------------------------------
#define ASTR 36
#define BSTR 136
#define KTILE 32

__global__ __launch_bounds__(256)
void gemm_tf32(const float* __restrict__ A, const float* __restrict__ B,
               const float* __restrict__ bias, float* __restrict__ C,
               int M, int N, int K)
{
    extern __shared__ uint32_t sm[];
    uint32_t* As = sm;                  // [2][128*ASTR]
    uint32_t* Bs = sm + 2 * 128 * ASTR; // [2][KTILE*BSTR]

    const int tid  = threadIdx.x;
    const int lane = tid & 31;
    const int wid  = tid >> 5;
    const int wm   = wid & 3;   // warp row   (32 rows each)
    const int wn   = wid >> 2;  // warp col   (64 cols each)
    const int lr   = lane >> 2; // 0..7
    const int lc   = lane & 3;  // 0..3
    const int row0 = blockIdx.y * 128;
    const int col0 = blockIdx.x * 128;

    float acc[2][8][4];
#pragma unroll
    for (int mt = 0; mt < 2; mt++)
#pragma unroll
        for (int nt = 0; nt < 8; nt++)
#pragma unroll
            for (int j = 0; j < 4; j++) acc[mt][nt][j] = 0.f;

    // global-load mapping
    const int arow = tid >> 1;          // 0..127
    const int acol = (tid & 1) * 16;    // 0 or 16
    const int brow = tid >> 3;          // 0..31
    const int bcol = (tid & 7) * 16;    // 0..112

    const float* Ag = A + (size_t)(row0 + arow) * K + acol;
    const float* Bg = B + (size_t)brow * N + col0 + bcol;

    float4 ra[4], rb[4];
#pragma unroll
    for (int i = 0; i < 4; i++) ra[i] = *(const float4*)(Ag + i * 4);
#pragma unroll
    for (int i = 0; i < 4; i++) rb[i] = *(const float4*)(Bg + i * 4);

    auto stA = [&](int buf) {
        uint32_t* p = As + buf * 128 * ASTR + arow * ASTR + acol;
#pragma unroll
        for (int i = 0; i < 4; i++)
            *(uint4*)(p + i * 4) =
                make_uint4(f2tf(ra[i].x), f2tf(ra[i].y), f2tf(ra[i].z), f2tf(ra[i].w));
    };
    auto stB = [&](int buf) {
        uint32_t* p = Bs + buf * KTILE * BSTR + brow * BSTR + bcol;
#pragma unroll
        for (int i = 0; i < 4; i++)
            *(uint4*)(p + i * 4) =
                make_uint4(f2tf(rb[i].x), f2tf(rb[i].y), f2tf(rb[i].z), f2tf(rb[i].w));
    };

    stA(0); stB(0);
    __syncthreads();

    const int kIters = K / KTILE;
    for (int it = 0; it < kIters; ++it) {
        if (it + 1 < kIters) {
            const float* Ag2 = Ag + (it + 1) * KTILE;
            const float* Bg2 = Bg + (size_t)(it + 1) * KTILE * N;
#pragma unroll
            for (int i = 0; i < 4; i++) ra[i] = *(const float4*)(Ag2 + i * 4);
#pragma unroll
            for (int i = 0; i < 4; i++) rb[i] = *(const float4*)(Bg2 + i * 4);
        }

        const uint32_t* Ab = As + (it & 1) * 128 * ASTR;
        const uint32_t* Bb = Bs + (it & 1) * KTILE * BSTR;

#pragma unroll
        for (int kk = 0; kk < 4; ++kk) {
            uint32_t af[2][4];
#pragma unroll
            for (int mt = 0; mt < 2; mt++) {
                int r = wm * 32 + mt * 16 + lr;
                int c = kk * 8 + lc;
                af[mt][0] = Ab[r * ASTR + c];
                af[mt][1] = Ab[(r + 8) * ASTR + c];
                af[mt][2] = Ab[r * ASTR + c + 4];
                af[mt][3] = Ab[(r + 8) * ASTR + c + 4];
            }
#pragma unroll
            for (int nt = 0; nt < 8; nt++) {
                uint32_t bf[2];
                int cc = wn * 64 + nt * 8 + lr;
                int rr = kk * 8 + lc;
                bf[0] = Bb[rr * BSTR + cc];
                bf[1] = Bb[(rr + 4) * BSTR + cc];
                mma_tf32(acc[0][nt], af[0], bf);
                mma_tf32(acc[1][nt], af[1], bf);
            }
        }

        if (it + 1 < kIters) { stA((it + 1) & 1); stB((it + 1) & 1); }
        __syncthreads();
    }

    // epilogue
#pragma unroll
    for (int mt = 0; mt < 2; mt++) {
        int r = row0 + wm * 32 + mt * 16 + lr;
#pragma unroll
        for (int nt = 0; nt < 8; nt++) {
            int c = col0 + wn * 64 + nt * 8 + 2 * lc;
            float bx = 0.f, by = 0.f;
            if (bias) { bx = bias[c]; by = bias[c + 1]; }
            *(float2*)(C + (size_t)r * N + c) =
                make_float2(acc[mt][nt][0] + bx, acc[mt][nt][1] + by);
            *(float2*)(C + (size_t)(r + 8) * N + c) =
                make_float2(acc[mt][nt][2] + bx, acc[mt][nt][3] + by);
        }
    }
}

// ---------------------------------------------------------------------------
// Causal flash attention, tf32 tensor cores, fp32 online softmax.
// CTA = 64 q rows for one (b,h); 4 warps, each owns 16 q rows.
// K-tiles of 64. S = Q@K^T and O += P@V both via m16n8k8 tf32 mma.
// P goes through smem (acc layout -> A-operand layout).
// ---------------------------------------------------------------------------
#define QSTR 68   // Q/K/P smem stride (mod32=4 -> conflict-free frag loads)
#define VSTR 72   // V smem stride (mod32=8 -> conflict-free B-operand loads)

__global__ __launch_bounds__(128)
void attn_tf32(const float* __restrict__ Q, const float* __restrict__ K,
               const float* __restrict__ V, float* __restrict__ ctx)
{
    extern __shared__ uint32_t sm[];
    uint32_t* Qs = sm;                  // [64][QSTR]
    uint32_t* Ks = Qs + 64 * QSTR;      // [64][QSTR]
    uint32_t* Vs = Ks + 64 * QSTR;      // [64][VSTR]
    uint32_t* Ps = Vs + 64 * VSTR;      // [64][QSTR]

    const int tid  = threadIdx.x;
    const int lane = tid & 31;
    const int wid  = tid >> 5;
    const int lr   = lane >> 2;
    const int lc   = lane & 3;
    const int qt   = gridDim.x - 1 - blockIdx.x;  // heavy tiles first
    const int h    = blockIdx.y;
    const int b    = blockIdx.z;

    const size_t base = (size_t)(b * SEQ) * D_MODEL + h * DHEAD;
    const float* Qg = Q + base + (size_t)qt * 64 * D_MODEL;

    // Load Q (pre-scaled by 1/8, cvt to tf32)
    {
        int row = tid >> 1;
        int c0  = (tid & 1) * 32;
        const float* src = Qg + (size_t)row * D_MODEL + c0;
        uint32_t*    dst = Qs + row * QSTR + c0;
#pragma unroll
        for (int i = 0; i < 8; i++) {
            float4 v = *(const float4*)(src + i * 4);
            *(uint4*)(dst + i * 4) = make_uint4(
                f2tf(v.x * 0.125f), f2tf(v.y * 0.125f),
                f2tf(v.z * 0.125f), f2tf(v.w * 0.125f));
        }
    }

    float oacc[8][4];
#pragma unroll
    for (int nt = 0; nt < 8; nt++)
#pragma unroll
        for (int j = 0; j < 4; j++) oacc[nt][j] = 0.f;
    float m0 = -1e30f, m1 = -1e30f, l0 = 0.f, l1 = 0.f;

    for (int kt = 0; kt <= qt; ++kt) {
        __syncthreads();   // protect Ks/Vs reuse (and Q visibility on iter 0)
        {
            const float* Kg = K + base + (size_t)kt * 64 * D_MODEL;
            const float* Vg = V + base + (size_t)kt * 64 * D_MODEL;
            int row = tid >> 1;
            int c0  = (tid & 1) * 32;
            const float* ks = Kg + (size_t)row * D_MODEL + c0;
            const float* vs = Vg + (size_t)row * D_MODEL + c0;
            uint32_t* kd = Ks + row * QSTR + c0;
            uint32_t* vd = Vs + row * VSTR + c0;
#pragma unroll
            for (int i = 0; i < 8; i++) {
                float4 kv = *(const float4*)(ks + i * 4);
                *(uint4*)(kd + i * 4) =
                    make_uint4(f2tf(kv.x), f2tf(kv.y), f2tf(kv.z), f2tf(kv.w));
                float4 vv = *(const float4*)(vs + i * 4);
                *(uint4*)(vd + i * 4) =
                    make_uint4(f2tf(vv.x), f2tf(vv.y), f2tf(vv.z), f2tf(vv.w));
            }
        }
        __syncthreads();

        // S = Q @ K^T  (16x64 per warp)
        float sacc[8][4];
#pragma unroll
        for (int nt = 0; nt < 8; nt++)
#pragma unroll
            for (int j = 0; j < 4; j++) sacc[nt][j] = 0.f;

#pragma unroll
        for (int kk = 0; kk < 8; ++kk) {
            uint32_t af[4];
            int r = wid * 16 + lr;
            int c = kk * 8 + lc;
            af[0] = Qs[r * QSTR + c];
            af[1] = Qs[(r + 8) * QSTR + c];
            af[2] = Qs[r * QSTR + c + 4];
            af[3] = Qs[(r + 8) * QSTR + c + 4];
#pragma unroll
            for (int nt = 0; nt < 8; nt++) {
                uint32_t bf[2];
                int key = nt * 8 + lr;
                bf[0] = Ks[key * QSTR + kk * 8 + lc];
                bf[1] = Ks[key * QSTR + kk * 8 + lc + 4];
                mma_tf32(sacc[nt], af, bf);
            }
        }

        // causal mask on the diagonal tile
        if (kt == qt) {
            int rg = wid * 16 + lr;
#pragma unroll
            for (int nt = 0; nt < 8; nt++) {
                int cg = nt * 8 + 2 * lc;
                if (cg     > rg)     sacc[nt][0] = -1e30f;
                if (cg + 1 > rg)     sacc[nt][1] = -1e30f;
                if (cg     > rg + 8) sacc[nt][2] = -1e30f;
                if (cg + 1 > rg + 8) sacc[nt][3] = -1e30f;
            }
        }

        // online softmax (rows lane/4 and lane/4+8; reduce over 4-lane groups)
        float rm0 = -1e30f, rm1 = -1e30f;
#pragma unroll
        for (int nt = 0; nt < 8; nt++) {
            rm0 = fmaxf(rm0, fmaxf(sacc[nt][0], sacc[nt][1]));
            rm1 = fmaxf(rm1, fmaxf(sacc[nt][2], sacc[nt][3]));
        }
        rm0 = fmaxf(rm0, __shfl_xor_sync(0xffffffffu, rm0, 1));
        rm0 = fmaxf(rm0, __shfl_xor_sync(0xffffffffu, rm0, 2));
        rm1 = fmaxf(rm1, __shfl_xor_sync(0xffffffffu, rm1, 1));
        rm1 = fmaxf(rm1, __shfl_xor_sync(0xffffffffu, rm1, 2));

        float mn0 = fmaxf(m0, rm0), mn1 = fmaxf(m1, rm1);
        float sc0 = __expf(m0 - mn0), sc1 = __expf(m1 - mn1);
        float ls0 = 0.f, ls1 = 0.f;
#pragma unroll
        for (int nt = 0; nt < 8; nt++) {
            sacc[nt][0] = __expf(sacc[nt][0] - mn0);
            sacc[nt][1] = __expf(sacc[nt][1] - mn0);
            sacc[nt][2] = __expf(sacc[nt][2] - mn1);
            sacc[nt][3] = __expf(sacc[nt][3] - mn1);
            ls0 += sacc[nt][0] + sacc[nt][1];
            ls1 += sacc[nt][2] + sacc[nt][3];
        }
        ls0 += __shfl_xor_sync(0xffffffffu, ls0, 1);
        ls0 += __shfl_xor_sync(0xffffffffu, ls0, 2);
        ls1 += __shfl_xor_sync(0xffffffffu, ls1, 1);
        ls1 += __shfl_xor_sync(0xffffffffu, ls1, 2);
        l0 = l0 * sc0 + ls0; m0 = mn0;
        l1 = l1 * sc1 + ls1; m1 = mn1;
#pragma unroll
        for (int nt = 0; nt < 8; nt++) {
            oacc[nt][0] *= sc0; oacc[nt][1] *= sc0;
            oacc[nt][2] *= sc1; oacc[nt][3] *= sc1;
        }

        // P -> smem (own warp's 16 rows), cvt to tf32
        {
            int r = wid * 16 + lr;
#pragma unroll
            for (int nt = 0; nt < 8; nt++) {
                int c = nt * 8 + 2 * lc;
                *(uint2*)(Ps + r * QSTR + c) =
                    make_uint2(f2tf(sacc[nt][0]), f2tf(sacc[nt][1]));
                *(uint2*)(Ps + (r + 8) * QSTR + c) =
                    make_uint2(f2tf(sacc[nt][2]), f2tf(sacc[nt][3]));
            }
        }
        __syncwarp();

        // O += P @ V
#pragma unroll
        for (int kk = 0; kk < 8; ++kk) {
            uint32_t af[4];
            int r = wid * 16 + lr;
            int c = kk * 8 + lc;
            af[0] = Ps[r * QSTR + c];
            af[1] = Ps[(r + 8) * QSTR + c];
            af[2] = Ps[r * QSTR + c + 4];
            af[3] = Ps[(r + 8) * QSTR + c + 4];
#pragma unroll
            for (int nt = 0; nt < 8; nt++) {
                uint32_t bf[2];
                int krow = kk * 8 + lc;
                bf[0] = Vs[krow * VSTR + nt * 8 + lr];
                bf[1] = Vs[(krow + 4) * VSTR + nt * 8 + lr];
                mma_tf32(oacc[nt], af, bf);
            }
        }
    }

    // finalize
    float inv0 = 1.f / l0, inv1 = 1.f / l1;
    float* Cg = ctx + base + (size_t)qt * 64 * D_MODEL;
    int r = wid * 16 + lr;
#pragma unroll
    for (int nt = 0; nt < 8; nt++) {
        int c = nt * 8 + 2 * lc;
        *(float2*)(Cg + (size_t)r * D_MODEL + c) =
            make_float2(oacc[nt][0] * inv0, oacc[nt][1] * inv0);
        *(float2*)(Cg + (size_t)(r + 8) * D_MODEL + c) =
            make_float2(oacc[nt][2] * inv1, oacc[nt][3] * inv1);
    }
}

// ---------------------------------------------------------------------------
extern "C" void kernel_launch(void* const* d_in, const int* in_sizes, int n_in,
                              void* d_out, int out_size)
{
    const float* x  = (const float*)d_in[0];
    const float* Wq = (const float*)d_in[1];
    const float* Wk = (const float*)d_in[2];
    const float* Wv = (const float*)d_in[3];
    const float* Wo = (const float*)d_in[4];
    const float* bo = (const float*)d_in[5];
    float* out = (float*)d_out;

    float *Qb, *Kb, *Vb, *Cb;
    cudaGetSymbolAddress((void**)&Qb, g_Q);
    cudaGetSymbolAddress((void**)&Kb, g_K);
    cudaGetSymbolAddress((void**)&Vb, g_V);
    cudaGetSymbolAddress((void**)&Cb, g_ctx);

    const int gsmem = (2 * 128 * ASTR + 2 * KTILE * BSTR) * 4;      // 71680 B
    const int asmem = (3 * 64 * QSTR + 64 * VSTR) * 4;              // 70656 B
    cudaFuncSetAttribute(gemm_tf32, cudaFuncAttributeMaxDynamicSharedMemorySize, gsmem);
    cudaFuncSetAttribute(attn_tf32, cudaFuncAttributeMaxDynamicSharedMemorySize, asmem);

    dim3 ggrid(D_MODEL / 128, BT / 128);   // (8, 32)
    gemm_tf32<<<ggrid, 256, gsmem>>>(x, Wq, nullptr, Qb, BT, D_MODEL, D_MODEL);
    gemm_tf32<<<ggrid, 256, gsmem>>>(x, Wk, nullptr, Kb, BT, D_MODEL, D_MODEL);
    gemm_tf32<<<ggrid, 256, gsmem>>>(x, Wv, nullptr, Vb, BT, D_MODEL, D_MODEL);

    dim3 agrid(SEQ / 64, NHEADS, BATCH);   // (32, 16, 2)
    attn_tf32<<<agrid, 128, asmem>>>(Qb, Kb, Vb, Cb);

    gemm_tf32<<<ggrid, 256, gsmem>>>(Cb, Wo, bo, out, BT, D_MODEL, D_MODEL);
}

// round 3
// speedup vs baseline: 2.4374x; 1.3132x over previous
#include <cuda_runtime.h>
#include <cstdint>

#define D_MODEL 1024
#define NHEADS  16
#define DHEAD   64
#define BATCH   2
#define SEQ     2048
#define BT      (BATCH * SEQ)

// Scratch (allocation-free rule: __device__ globals)
__device__ float g_Q[BT * D_MODEL];   // tf32-rounded bits, pre-scaled by 1/8
__device__ float g_K[BT * D_MODEL];   // tf32-rounded bits
__device__ float g_V[BT * D_MODEL];   // tf32-rounded bits
__device__ float g_ctx[BT * D_MODEL]; // fp32

__device__ __forceinline__ uint32_t f2tf(float f) {
    uint32_t u;
    asm("cvt.rna.tf32.f32 %0, %1;" : "=r"(u) : "f"(f));
    return u;
}

__device__ __forceinline__ void mma_tf32(float* c, const uint32_t* a, const uint32_t* b) {
    asm volatile(
        "mma.sync.aligned.m16n8k8.row.col.f32.tf32.tf32.f32 "
        "{%0,%1,%2,%3},{%4,%5,%6,%7},{%8,%9},{%0,%1,%2,%3};"
        : "+f"(c[0]), "+f"(c[1]), "+f"(c[2]), "+f"(c[3])
        : "r"(a[0]), "r"(a[1]), "r"(a[2]), "r"(a[3]), "r"(b[0]), "r"(b[1]));
}

__device__ __forceinline__ void cp_async16(uint32_t dst_sa, const void* src) {
    asm volatile("cp.async.ca.shared.global [%0], [%1], 16;" :: "r"(dst_sa), "l"(src));
}
__device__ __forceinline__ void cp_commit() { asm volatile("cp.async.commit_group;"); }

// ---------------------------------------------------------------------------
// tf32 GEMM: C[M,N] = A[M,K] @ B[K,N] (+bias). 128x128 CTA tile, BK=32,
// 256 threads = 8 warps as 4(m)x2(n), warp tile 32x64. Double-buffered smem.
// mode: 0 = fp32 + bias (final proj); 1 = tf32-rounded bits; 2 = tf32 bits * 0.125
// ---------------------------------------------------------------------------
#define ASTR 36
#define BSTR 136
#define KTILE 32

__global__ __launch_bounds__(256)
void gemm_tf32(const float* __restrict__ A, const float* __restrict__ B,
               const float* __restrict__ bias, float* __restrict__ C,
               int M, int N, int K, int mode)
{
    extern __shared__ uint32_t sm[];
    uint32_t* As = sm;                  // [2][128*ASTR]
    uint32_t* Bs = sm + 2 * 128 * ASTR; // [2][KTILE*BSTR]

    const int tid  = threadIdx.x;
    const int lane = tid & 31;
    const int wid  = tid >> 5;
    const int wm   = wid & 3;
    const int wn   = wid >> 2;
    const int lr   = lane >> 2;
    const int lc   = lane & 3;
    const int row0 = blockIdx.y * 128;
    const int col0 = blockIdx.x * 128;

    float acc[2][8][4];
#pragma unroll
    for (int mt = 0; mt < 2; mt++)
#pragma unroll
        for (int nt = 0; nt < 8; nt++)
#pragma unroll
            for (int j = 0; j < 4; j++) acc[mt][nt][j] = 0.f;

    const int arow = tid >> 1;
    const int acol = (tid & 1) * 16;
    const int brow = tid >> 3;
    const int bcol = (tid & 7) * 16;

    const float* Ag = A + (size_t)(row0 + arow) * K + acol;
    const float* Bg = B + (size_t)brow * N + col0 + bcol;

    float4 ra[4], rb[4];
#pragma unroll
    for (int i = 0; i < 4; i++) ra[i] = *(const float4*)(Ag + i * 4);
#pragma unroll
    for (int i = 0; i < 4; i++) rb[i] = *(const float4*)(Bg + i * 4);

    auto stA = [&](int buf) {
        uint32_t* p = As + buf * 128 * ASTR + arow * ASTR + acol;
#pragma unroll
        for (int i = 0; i < 4; i++)
            *(uint4*)(p + i * 4) =
                make_uint4(f2tf(ra[i].x), f2tf(ra[i].y), f2tf(ra[i].z), f2tf(ra[i].w));
    };
    auto stB = [&](int buf) {
        uint32_t* p = Bs + buf * KTILE * BSTR + brow * BSTR + bcol;
#pragma unroll
        for (int i = 0; i < 4; i++)
            *(uint4*)(p + i * 4) =
                make_uint4(f2tf(rb[i].x), f2tf(rb[i].y), f2tf(rb[i].z), f2tf(rb[i].w));
    };

    stA(0); stB(0);
    __syncthreads();

    const int kIters = K / KTILE;
    for (int it = 0; it < kIters; ++it) {
        if (it + 1 < kIters) {
            const float* Ag2 = Ag + (it + 1) * KTILE;
            const float* Bg2 = Bg + (size_t)(it + 1) * KTILE * N;
#pragma unroll
            for (int i = 0; i < 4; i++) ra[i] = *(const float4*)(Ag2 + i * 4);
#pragma unroll
            for (int i = 0; i < 4; i++) rb[i] = *(const float4*)(Bg2 + i * 4);
        }

        const uint32_t* Ab = As + (it & 1) * 128 * ASTR;
        const uint32_t* Bb = Bs + (it & 1) * KTILE * BSTR;

#pragma unroll
        for (int kk = 0; kk < 4; ++kk) {
            uint32_t af[2][4];
#pragma unroll
            for (int mt = 0; mt < 2; mt++) {
                int r = wm * 32 + mt * 16 + lr;
                int c = kk * 8 + lc;
                af[mt][0] = Ab[r * ASTR + c];
                af[mt][1] = Ab[(r + 8) * ASTR + c];
                af[mt][2] = Ab[r * ASTR + c + 4];
                af[mt][3] = Ab[(r + 8) * ASTR + c + 4];
            }
#pragma unroll
            for (int nt = 0; nt < 8; nt++) {
                uint32_t bf[2];
                int cc = wn * 64 + nt * 8 + lr;
                int rr = kk * 8 + lc;
                bf[0] = Bb[rr * BSTR + cc];
                bf[1] = Bb[(rr + 4) * BSTR + cc];
                mma_tf32(acc[0][nt], af[0], bf);
                mma_tf32(acc[1][nt], af[1], bf);
            }
        }

        if (it + 1 < kIters) { stA((it + 1) & 1); stB((it + 1) & 1); }
        __syncthreads();
    }

    // epilogue
#pragma unroll
    for (int mt = 0; mt < 2; mt++) {
        int r = row0 + wm * 32 + mt * 16 + lr;
#pragma unroll
        for (int nt = 0; nt < 8; nt++) {
            int c = col0 + wn * 64 + nt * 8 + 2 * lc;
            float v[4] = {acc[mt][nt][0], acc[mt][nt][1], acc[mt][nt][2], acc[mt][nt][3]};
            if (mode == 0) {
                float bx = bias[c], by = bias[c + 1];
                *(float2*)(C + (size_t)r * N + c) = make_float2(v[0] + bx, v[1] + by);
                *(float2*)(C + (size_t)(r + 8) * N + c) = make_float2(v[2] + bx, v[3] + by);
            } else {
                float s = (mode == 2) ? 0.125f : 1.0f;
                uint32_t* Cu = (uint32_t*)C;
                *(uint2*)(Cu + (size_t)r * N + c) =
                    make_uint2(f2tf(v[0] * s), f2tf(v[1] * s));
                *(uint2*)(Cu + (size_t)(r + 8) * N + c) =
                    make_uint2(f2tf(v[2] * s), f2tf(v[3] * s));
            }
        }
    }
}

// ---------------------------------------------------------------------------
// Causal flash attention, tf32 tensor cores, fp32 online softmax.
// CTA = 128 q rows for one (b,h); 8 warps, each owns 16 q rows.
// KV tiles of 64 keys, double-buffered via cp.async.
// Q/K/V arrive pre-rounded to tf32 (Q pre-scaled) -> no conversion in-loop.
// ---------------------------------------------------------------------------
#define QSTR 68   // stride mod32=4 -> conflict-free frag loads
#define VSTR 72   // stride mod32=8 -> conflict-free B-operand loads

__global__ __launch_bounds__(256)
void attn_tf32(const float* __restrict__ Q, const float* __restrict__ K,
               const float* __restrict__ V, float* __restrict__ ctx)
{
    extern __shared__ uint32_t sm[];
    uint32_t* Qs = sm;                     // [128][QSTR]
    uint32_t* Kd = Qs + 128 * QSTR;        // [2][64][QSTR]
    uint32_t* Vd = Kd + 2 * 64 * QSTR;     // [2][64][VSTR]
    uint32_t* Ps = Vd + 2 * 64 * VSTR;     // [128][QSTR]

    const int tid  = threadIdx.x;
    const int lane = tid & 31;
    const int wid  = tid >> 5;            // 0..7, rows 16*wid..16*wid+15
    const int lr   = lane >> 2;
    const int lc   = lane & 3;
    const int qt   = gridDim.x - 1 - blockIdx.x;  // heavy tiles first
    const int h    = blockIdx.y;
    const int b    = blockIdx.z;

    const size_t base = (size_t)(b * SEQ) * D_MODEL + h * DHEAD;
    const float* Qg = Q + base + (size_t)qt * 128 * D_MODEL;
    const float* Kg0 = K + base;
    const float* Vg0 = V + base;

    const uint32_t saK = (uint32_t)__cvta_generic_to_shared(Kd);
    const uint32_t saV = (uint32_t)__cvta_generic_to_shared(Vd);

    // cp.async mapping: thread -> (row = tid>>2, quarter = tid&3 -> 16 floats)
    const int krow = tid >> 2;
    const int kq16 = (tid & 3) * 16;

    auto copy_kv = [&](int buf, int kt) {
        const float* Kg = Kg0 + (size_t)kt * 64 * D_MODEL + (size_t)krow * D_MODEL + kq16;
        const float* Vg = Vg0 + (size_t)kt * 64 * D_MODEL + (size_t)krow * D_MODEL + kq16;
        uint32_t kd = saK + (uint32_t)(((buf * 64 + krow) * QSTR + kq16) * 4);
        uint32_t vd = saV + (uint32_t)(((buf * 64 + krow) * VSTR + kq16) * 4);
#pragma unroll
        for (int i = 0; i < 4; i++) cp_async16(kd + i * 16, Kg + i * 4);
#pragma unroll
        for (int i = 0; i < 4; i++) cp_async16(vd + i * 16, Vg + i * 4);
    };

    // Load Q tile (raw bit copy, already tf32+prescaled)
    for (int i = tid; i < 128 * 16; i += 256) {
        int row = i >> 4, c4 = (i & 15) << 2;
        *(uint4*)&Qs[row * QSTR + c4] = *(const uint4*)(Qg + (size_t)row * D_MODEL + c4);
    }

    const int nkt = 2 * qt + 2;
    copy_kv(0, 0);
    cp_commit();

    float oacc[8][4];
#pragma unroll
    for (int nt = 0; nt < 8; nt++)
#pragma unroll
        for (int j = 0; j < 4; j++) oacc[nt][j] = 0.f;
    float m0 = -1e30f, m1 = -1e30f, l0 = 0.f, l1 = 0.f;

    const int rg0 = qt * 128 + wid * 16 + lr;   // this thread's global q rows (and +8)

    for (int kt = 0; kt < nkt; ++kt) {
        if (kt + 1 < nkt) { copy_kv((kt + 1) & 1, kt + 1); cp_commit(); }
        if (kt + 1 < nkt) asm volatile("cp.async.wait_group 1;" ::: "memory");
        else              asm volatile("cp.async.wait_group 0;" ::: "memory");
        __syncthreads();

        const uint32_t* Ks = Kd + (kt & 1) * 64 * QSTR;
        const uint32_t* Vs = Vd + (kt & 1) * 64 * VSTR;

        // S = Q @ K^T (16x64 per warp)
        float sacc[8][4];
#pragma unroll
        for (int nt = 0; nt < 8; nt++)
#pragma unroll
            for (int j = 0; j < 4; j++) sacc[nt][j] = 0.f;

#pragma unroll
        for (int kk = 0; kk < 8; ++kk) {
            uint32_t af[4];
            int r = wid * 16 + lr;
            int c = kk * 8 + lc;
            af[0] = Qs[r * QSTR + c];
            af[1] = Qs[(r + 8) * QSTR + c];
            af[2] = Qs[r * QSTR + c + 4];
            af[3] = Qs[(r + 8) * QSTR + c + 4];
#pragma unroll
            for (int nt = 0; nt < 8; nt++) {
                uint32_t bf[2];
                int key = nt * 8 + lr;
                bf[0] = Ks[key * QSTR + kk * 8 + lc];
                bf[1] = Ks[key * QSTR + kk * 8 + lc + 4];
                mma_tf32(sacc[nt], af, bf);
            }
        }

        // causal mask (only near the diagonal)
        if (kt >= 2 * qt) {
            int cbase = kt * 64;
#pragma unroll
            for (int nt = 0; nt < 8; nt++) {
                int cg = cbase + nt * 8 + 2 * lc;
                if (cg     > rg0)     sacc[nt][0] = -1e30f;
                if (cg + 1 > rg0)     sacc[nt][1] = -1e30f;
                if (cg     > rg0 + 8) sacc[nt][2] = -1e30f;
                if (cg + 1 > rg0 + 8) sacc[nt][3] = -1e30f;
            }
        }

        // online softmax
        float rm0 = -1e30f, rm1 = -1e30f;
#pragma unroll
        for (int nt = 0; nt < 8; nt++) {
            rm0 = fmaxf(rm0, fmaxf(sacc[nt][0], sacc[nt][1]));
            rm1 = fmaxf(rm1, fmaxf(sacc[nt][2], sacc[nt][3]));
        }
        rm0 = fmaxf(rm0, __shfl_xor_sync(0xffffffffu, rm0, 1));
        rm0 = fmaxf(rm0, __shfl_xor_sync(0xffffffffu, rm0, 2));
        rm1 = fmaxf(rm1, __shfl_xor_sync(0xffffffffu, rm1, 1));
        rm1 = fmaxf(rm1, __shfl_xor_sync(0xffffffffu, rm1, 2));

        float mn0 = fmaxf(m0, rm0), mn1 = fmaxf(m1, rm1);
        float sc0 = __expf(m0 - mn0), sc1 = __expf(m1 - mn1);
        float ls0 = 0.f, ls1 = 0.f;
#pragma unroll
        for (int nt = 0; nt < 8; nt++) {
            sacc[nt][0] = __expf(sacc[nt][0] - mn0);
            sacc[nt][1] = __expf(sacc[nt][1] - mn0);
            sacc[nt][2] = __expf(sacc[nt][2] - mn1);
            sacc[nt][3] = __expf(sacc[nt][3] - mn1);
            ls0 += sacc[nt][0] + sacc[nt][1];
            ls1 += sacc[nt][2] + sacc[nt][3];
        }
        ls0 += __shfl_xor_sync(0xffffffffu, ls0, 1);
        ls0 += __shfl_xor_sync(0xffffffffu, ls0, 2);
        ls1 += __shfl_xor_sync(0xffffffffu, ls1, 1);
        ls1 += __shfl_xor_sync(0xffffffffu, ls1, 2);
        l0 = l0 * sc0 + ls0; m0 = mn0;
        l1 = l1 * sc1 + ls1; m1 = mn1;
#pragma unroll
        for (int nt = 0; nt < 8; nt++) {
            oacc[nt][0] *= sc0; oacc[nt][1] *= sc0;
            oacc[nt][2] *= sc1; oacc[nt][3] *= sc1;
        }

        // P -> smem (own warp's 16 rows), cvt to tf32
        {
            int r = wid * 16 + lr;
#pragma unroll
            for (int nt = 0; nt < 8; nt++) {
                int c = nt * 8 + 2 * lc;
                *(uint2*)(Ps + r * QSTR + c) =
                    make_uint2(f2tf(sacc[nt][0]), f2tf(sacc[nt][1]));
                *(uint2*)(Ps + (r + 8) * QSTR + c) =
                    make_uint2(f2tf(sacc[nt][2]), f2tf(sacc[nt][3]));
            }
        }
        __syncwarp();

        // O += P @ V
#pragma unroll
        for (int kk = 0; kk < 8; ++kk) {
            uint32_t af[4];
            int r = wid * 16 + lr;
            int c = kk * 8 + lc;
            af[0] = Ps[r * QSTR + c];
            af[1] = Ps[(r + 8) * QSTR + c];
            af[2] = Ps[r * QSTR + c + 4];
            af[3] = Ps[(r + 8) * QSTR + c + 4];
#pragma unroll
            for (int nt = 0; nt < 8; nt++) {
                uint32_t bf[2];
                int krow2 = kk * 8 + lc;
                bf[0] = Vs[krow2 * VSTR + nt * 8 + lr];
                bf[1] = Vs[(krow2 + 4) * VSTR + nt * 8 + lr];
                mma_tf32(oacc[nt], af, bf);
            }
        }
        __syncthreads();   // compute done before this buffer is overwritten
    }

    // finalize
    float inv0 = 1.f / l0, inv1 = 1.f / l1;
    float* Cg = ctx + base + (size_t)qt * 128 * D_MODEL;
    int r = wid * 16 + lr;
#pragma unroll
    for (int nt = 0; nt < 8; nt++) {
        int c = nt * 8 + 2 * lc;
        *(float2*)(Cg + (size_t)r * D_MODEL + c) =
            make_float2(oacc[nt][0] * inv0, oacc[nt][1] * inv0);
        *(float2*)(Cg + (size_t)(r + 8) * D_MODEL + c) =
            make_float2(oacc[nt][2] * inv1, oacc[nt][3] * inv1);
    }
}

// ---------------------------------------------------------------------------
extern "C" void kernel_launch(void* const* d_in, const int* in_sizes, int n_in,
                              void* d_out, int out_size)
{
    const float* x  = (const float*)d_in[0];
    const float* Wq = (const float*)d_in[1];
    const float* Wk = (const float*)d_in[2];
    const float* Wv = (const float*)d_in[3];
    const float* Wo = (const float*)d_in[4];
    const float* bo = (const float*)d_in[5];
    float* out = (float*)d_out;

    float *Qb, *Kb, *Vb, *Cb;
    cudaGetSymbolAddress((void**)&Qb, g_Q);
    cudaGetSymbolAddress((void**)&Kb, g_K);
    cudaGetSymbolAddress((void**)&Vb, g_V);
    cudaGetSymbolAddress((void**)&Cb, g_ctx);

    const int gsmem = (2 * 128 * ASTR + 2 * KTILE * BSTR) * 4;                 // 71680 B
    const int asmem = (128 * QSTR + 2 * 64 * QSTR + 2 * 64 * VSTR + 128 * QSTR) * 4; // 141312 B
    cudaFuncSetAttribute(gemm_tf32, cudaFuncAttributeMaxDynamicSharedMemorySize, gsmem);
    cudaFuncSetAttribute(attn_tf32, cudaFuncAttributeMaxDynamicSharedMemorySize, asmem);

    dim3 ggrid(D_MODEL / 128, BT / 128);   // (8, 32)
    gemm_tf32<<<ggrid, 256, gsmem>>>(x, Wq, nullptr, Qb, BT, D_MODEL, D_MODEL, 2);
    gemm_tf32<<<ggrid, 256, gsmem>>>(x, Wk, nullptr, Kb, BT, D_MODEL, D_MODEL, 1);
    gemm_tf32<<<ggrid, 256, gsmem>>>(x, Wv, nullptr, Vb, BT, D_MODEL, D_MODEL, 1);

    dim3 agrid(SEQ / 128, NHEADS, BATCH);  // (16, 16, 2)
    attn_tf32<<<agrid, 256, asmem>>>(Qb, Kb, Vb, Cb);

    gemm_tf32<<<ggrid, 256, gsmem>>>(Cb, Wo, bo, out, BT, D_MODEL, D_MODEL, 0);
}

// round 4
// speedup vs baseline: 2.5027x; 1.0268x over previous
#include <cuda_runtime.h>
#include <cstdint>

#define D_MODEL 1024
#define NHEADS  16
#define DHEAD   64
#define BATCH   2
#define SEQ     2048
#define BT      (BATCH * SEQ)

// Scratch (allocation-free rule: __device__ globals)
__device__ float g_X [BT * D_MODEL];        // x, tf32-rounded bits
__device__ float g_Wq[D_MODEL * D_MODEL];   // weights, tf32-rounded bits
__device__ float g_Wk[D_MODEL * D_MODEL];
__device__ float g_Wv[D_MODEL * D_MODEL];
__device__ float g_Wo[D_MODEL * D_MODEL];
__device__ float g_Q [BT * D_MODEL];        // tf32 bits, pre-scaled by 1/8
__device__ float g_K [BT * D_MODEL];        // tf32 bits
__device__ float g_V [BT * D_MODEL];        // tf32 bits
__device__ float g_ctx[BT * D_MODEL];       // tf32 bits (attn output)

__device__ __forceinline__ uint32_t f2tf(float f) {
    uint32_t u;
    asm("cvt.rna.tf32.f32 %0, %1;" : "=r"(u) : "f"(f));
    return u;
}

__device__ __forceinline__ void mma_tf32(float* c, const uint32_t* a, const uint32_t* b) {
    asm volatile(
        "mma.sync.aligned.m16n8k8.row.col.f32.tf32.tf32.f32 "
        "{%0,%1,%2,%3},{%4,%5,%6,%7},{%8,%9},{%0,%1,%2,%3};"
        : "+f"(c[0]), "+f"(c[1]), "+f"(c[2]), "+f"(c[3])
        : "r"(a[0]), "r"(a[1]), "r"(a[2]), "r"(a[3]), "r"(b[0]), "r"(b[1]));
}

__device__ __forceinline__ void cp_async16(uint32_t dst_sa, const void* src) {
    asm volatile("cp.async.ca.shared.global [%0], [%1], 16;" :: "r"(dst_sa), "l"(src));
}
__device__ __forceinline__ void cp_commit() { asm volatile("cp.async.commit_group;"); }
__device__ __forceinline__ void cp_wait1()  { asm volatile("cp.async.wait_group 1;" ::: "memory"); }

// ---------------------------------------------------------------------------
// RNA-round fp32 -> tf32 bits (vectorized elementwise)
// ---------------------------------------------------------------------------
__global__ __launch_bounds__(256)
void round_tf32(const float* __restrict__ in, float* __restrict__ out, int n4)
{
    int i = blockIdx.x * blockDim.x + threadIdx.x;
    if (i < n4) {
        float4 v = ((const float4*)in)[i];
        ((uint4*)out)[i] = make_uint4(f2tf(v.x), f2tf(v.y), f2tf(v.z), f2tf(v.w));
    }
}

// ---------------------------------------------------------------------------
// tf32 GEMM: C = A[4096,1024] @ B[1024,1024]. Inputs pre-rounded tf32 bits.
// 128x128 CTA tile, BK=32, 3-stage cp.async, 256 thr = 8 warps (4m x 2n).
// blockIdx.z selects B/C (fused QKV). mode: 0=fp32+bias, 1=tf32 bits, 2=bits*0.125
// ---------------------------------------------------------------------------
#define ASTR 36
#define BSTR 136
#define KTILE 32
#define GSTAGES 3
#define A_STG (128 * ASTR)
#define B_STG (KTILE * BSTR)

__global__ __launch_bounds__(256, 2)
void gemm_tf32(const float* __restrict__ A,
               const float* __restrict__ B0, const float* __restrict__ B1,
               const float* __restrict__ B2,
               float* __restrict__ C0, float* __restrict__ C1, float* __restrict__ C2,
               const float* __restrict__ bias, int mode0)
{
    extern __shared__ uint32_t sm[];
    uint32_t* As = sm;                       // [GSTAGES][A_STG]
    uint32_t* Bs = sm + GSTAGES * A_STG;     // [GSTAGES][B_STG]

    const int z = blockIdx.z;
    const float* B = (z == 0) ? B0 : (z == 1) ? B1 : B2;
    float*       C = (z == 0) ? C0 : (z == 1) ? C1 : C2;
    const int mode = (z == 0) ? mode0 : 1;

    const int tid  = threadIdx.x;
    const int lane = tid & 31;
    const int wid  = tid >> 5;
    const int wm   = wid & 3;
    const int wn   = wid >> 2;
    const int lr   = lane >> 2;
    const int lc   = lane & 3;
    const int row0 = blockIdx.y * 128;
    const int col0 = blockIdx.x * 128;

    const int arow = tid >> 1;
    const int acol = (tid & 1) * 16;
    const int brow = tid >> 3;
    const int bcol = (tid & 7) * 16;

    const float* Ag = A + (size_t)(row0 + arow) * D_MODEL + acol;
    const float* Bg = B + (size_t)brow * D_MODEL + col0 + bcol;
    const uint32_t saA = (uint32_t)__cvta_generic_to_shared(As) + (arow * ASTR + acol) * 4;
    const uint32_t saB = (uint32_t)__cvta_generic_to_shared(Bs) + (brow * BSTR + bcol) * 4;

    auto load_tile = [&](int t) {
        int s = t % GSTAGES;
        const float* a = Ag + t * KTILE;
        const float* b = Bg + (size_t)t * KTILE * D_MODEL;
        uint32_t da = saA + s * A_STG * 4;
        uint32_t db = saB + s * B_STG * 4;
#pragma unroll
        for (int i = 0; i < 4; i++) cp_async16(da + i * 16, a + i * 4);
#pragma unroll
        for (int i = 0; i < 4; i++) cp_async16(db + i * 16, b + i * 4);
    };

    load_tile(0); cp_commit();
    load_tile(1); cp_commit();

    float acc[2][8][4];
#pragma unroll
    for (int mt = 0; mt < 2; mt++)
#pragma unroll
        for (int nt = 0; nt < 8; nt++)
#pragma unroll
            for (int j = 0; j < 4; j++) acc[mt][nt][j] = 0.f;

    const int kIters = D_MODEL / KTILE;   // 32
    for (int it = 0; it < kIters; ++it) {
        cp_wait1();
        __syncthreads();
        if (it + 2 < kIters) load_tile(it + 2);
        cp_commit();

        const uint32_t* Ab = As + (it % GSTAGES) * A_STG;
        const uint32_t* Bb = Bs + (it % GSTAGES) * B_STG;

#pragma unroll
        for (int kk = 0; kk < 4; ++kk) {
            uint32_t af[2][4];
#pragma unroll
            for (int mt = 0; mt < 2; mt++) {
                int r = wm * 32 + mt * 16 + lr;
                int c = kk * 8 + lc;
                af[mt][0] = Ab[r * ASTR + c];
                af[mt][1] = Ab[(r + 8) * ASTR + c];
                af[mt][2] = Ab[r * ASTR + c + 4];
                af[mt][3] = Ab[(r + 8) * ASTR + c + 4];
            }
#pragma unroll
            for (int nt = 0; nt < 8; nt++) {
                uint32_t bf[2];
                int cc = wn * 64 + nt * 8 + lr;
                int rr = kk * 8 + lc;
                bf[0] = Bb[rr * BSTR + cc];
                bf[1] = Bb[(rr + 4) * BSTR + cc];
                mma_tf32(acc[0][nt], af[0], bf);
                mma_tf32(acc[1][nt], af[1], bf);
            }
        }
    }

    // epilogue
#pragma unroll
    for (int mt = 0; mt < 2; mt++) {
        int r = row0 + wm * 32 + mt * 16 + lr;
#pragma unroll
        for (int nt = 0; nt < 8; nt++) {
            int c = col0 + wn * 64 + nt * 8 + 2 * lc;
            float* v = acc[mt][nt];
            if (mode == 0) {
                float bx = bias[c], by = bias[c + 1];
                *(float2*)(C + (size_t)r * D_MODEL + c) = make_float2(v[0] + bx, v[1] + by);
                *(float2*)(C + (size_t)(r + 8) * D_MODEL + c) = make_float2(v[2] + bx, v[3] + by);
            } else {
                float s = (mode == 2) ? 0.125f : 1.0f;
                uint32_t* Cu = (uint32_t*)C;
                *(uint2*)(Cu + (size_t)r * D_MODEL + c) =
                    make_uint2(f2tf(v[0] * s), f2tf(v[1] * s));
                *(uint2*)(Cu + (size_t)(r + 8) * D_MODEL + c) =
                    make_uint2(f2tf(v[2] * s), f2tf(v[3] * s));
            }
        }
    }
}

// ---------------------------------------------------------------------------
// Causal flash attention, tf32 mma, fp32 online softmax.
// CTA = 128 q rows (8 warps x 16 rows); KV tiles of 32 keys, 3-stage cp.async.
// Inputs pre-rounded tf32 (Q pre-scaled by 1/8). Output: tf32-rounded ctx.
// ---------------------------------------------------------------------------
#define QSTR 68   // mod32=4 -> conflict-free A/B frag loads
#define VSTR 72   // mod32=8 -> conflict-free V B-operand loads
#define PSTR 36   // mod32=4 -> conflict-free P A-operand loads
#define KV   32
#define ASTAGES 3

__global__ __launch_bounds__(256, 2)
void attn_tf32(const float* __restrict__ Q, const float* __restrict__ K,
               const float* __restrict__ V, float* __restrict__ ctx)
{
    extern __shared__ uint32_t sm[];
    uint32_t* Qs = sm;                          // [128][QSTR]
    uint32_t* Ps = Qs + 128 * QSTR;             // [128][PSTR]
    uint32_t* Kd = Ps + 128 * PSTR;             // [3][KV][QSTR]
    uint32_t* Vd = Kd + ASTAGES * KV * QSTR;    // [3][KV][VSTR]

    const int tid  = threadIdx.x;
    const int lane = tid & 31;
    const int wid  = tid >> 5;
    const int lr   = lane >> 2;
    const int lc   = lane & 3;
    const int qt   = gridDim.x - 1 - blockIdx.x;  // heavy tiles first
    const int h    = blockIdx.y;
    const int b    = blockIdx.z;

    const size_t base = (size_t)(b * SEQ) * D_MODEL + h * DHEAD;
    const float* Qg  = Q + base + (size_t)qt * 128 * D_MODEL;
    const float* Kg0 = K + base;
    const float* Vg0 = V + base;

    const uint32_t saK = (uint32_t)__cvta_generic_to_shared(Kd);
    const uint32_t saV = (uint32_t)__cvta_generic_to_shared(Vd);

    // KV cp.async mapping: row = tid>>3 (0..31), col chunk = (tid&7)*8 floats
    const int krow = tid >> 3;
    const int kc8  = (tid & 7) * 8;

    auto copy_kv = [&](int t) {
        int s = t % ASTAGES;
        const float* Kg = Kg0 + ((size_t)t * KV + krow) * D_MODEL + kc8;
        const float* Vg = Vg0 + ((size_t)t * KV + krow) * D_MODEL + kc8;
        uint32_t kd = saK + ((s * KV + krow) * QSTR + kc8) * 4;
        uint32_t vd = saV + ((s * KV + krow) * VSTR + kc8) * 4;
        cp_async16(kd,      Kg);
        cp_async16(kd + 16, Kg + 4);
        cp_async16(vd,      Vg);
        cp_async16(vd + 16, Vg + 4);
    };

    // Load Q tile (raw bit copy, already tf32 + prescaled)
    for (int i = tid; i < 128 * 16; i += 256) {
        int row = i >> 4, c4 = (i & 15) << 2;
        *(uint4*)&Qs[row * QSTR + c4] = *(const uint4*)(Qg + (size_t)row * D_MODEL + c4);
    }

    const int nkt = 4 * qt + 4;
    copy_kv(0); cp_commit();
    copy_kv(1); cp_commit();

    float oacc[8][4];
#pragma unroll
    for (int nt = 0; nt < 8; nt++)
#pragma unroll
        for (int j = 0; j < 4; j++) oacc[nt][j] = 0.f;
    float m0 = -1e30f, m1 = -1e30f, l0 = 0.f, l1 = 0.f;

    const int rg0 = qt * 128 + wid * 16 + lr;  // this thread's global q rows (and +8)

    for (int kt = 0; kt < nkt; ++kt) {
        cp_wait1();
        __syncthreads();
        if (kt + 2 < nkt) copy_kv(kt + 2);
        cp_commit();

        const uint32_t* Ks = Kd + (kt % ASTAGES) * KV * QSTR;
        const uint32_t* Vs = Vd + (kt % ASTAGES) * KV * VSTR;

        // S = Q @ K^T : 16x32 per warp
        float sacc[4][4];
#pragma unroll
        for (int nt = 0; nt < 4; nt++)
#pragma unroll
            for (int j = 0; j < 4; j++) sacc[nt][j] = 0.f;

#pragma unroll
        for (int kk = 0; kk < 8; ++kk) {
            uint32_t af[4];
            int r = wid * 16 + lr;
            int c = kk * 8 + lc;
            af[0] = Qs[r * QSTR + c];
            af[1] = Qs[(r + 8) * QSTR + c];
            af[2] = Qs[r * QSTR + c + 4];
            af[3] = Qs[(r + 8) * QSTR + c + 4];
#pragma unroll
            for (int nt = 0; nt < 4; nt++) {
                uint32_t bf[2];
                int key = nt * 8 + lr;
                bf[0] = Ks[key * QSTR + kk * 8 + lc];
                bf[1] = Ks[key * QSTR + kk * 8 + lc + 4];
                mma_tf32(sacc[nt], af, bf);
            }
        }

        // causal mask near the diagonal (last 4 tiles)
        if (kt >= 4 * qt) {
            int cbase = kt * KV;
#pragma unroll
            for (int nt = 0; nt < 4; nt++) {
                int cg = cbase + nt * 8 + 2 * lc;
                if (cg     > rg0)     sacc[nt][0] = -1e30f;
                if (cg + 1 > rg0)     sacc[nt][1] = -1e30f;
                if (cg     > rg0 + 8) sacc[nt][2] = -1e30f;
                if (cg + 1 > rg0 + 8) sacc[nt][3] = -1e30f;
            }
        }

        // online softmax
        float rm0 = -1e30f, rm1 = -1e30f;
#pragma unroll
        for (int nt = 0; nt < 4; nt++) {
            rm0 = fmaxf(rm0, fmaxf(sacc[nt][0], sacc[nt][1]));
            rm1 = fmaxf(rm1, fmaxf(sacc[nt][2], sacc[nt][3]));
        }
        rm0 = fmaxf(rm0, __shfl_xor_sync(0xffffffffu, rm0, 1));
        rm0 = fmaxf(rm0, __shfl_xor_sync(0xffffffffu, rm0, 2));
        rm1 = fmaxf(rm1, __shfl_xor_sync(0xffffffffu, rm1, 1));
        rm1 = fmaxf(rm1, __shfl_xor_sync(0xffffffffu, rm1, 2));

        float mn0 = fmaxf(m0, rm0), mn1 = fmaxf(m1, rm1);
        float sc0 = __expf(m0 - mn0), sc1 = __expf(m1 - mn1);
        float ls0 = 0.f, ls1 = 0.f;
#pragma unroll
        for (int nt = 0; nt < 4; nt++) {
            sacc[nt][0] = __expf(sacc[nt][0] - mn0);
            sacc[nt][1] = __expf(sacc[nt][1] - mn0);
            sacc[nt][2] = __expf(sacc[nt][2] - mn1);
            sacc[nt][3] = __expf(sacc[nt][3] - mn1);
            ls0 += sacc[nt][0] + sacc[nt][1];
            ls1 += sacc[nt][2] + sacc[nt][3];
        }
        ls0 += __shfl_xor_sync(0xffffffffu, ls0, 1);
        ls0 += __shfl_xor_sync(0xffffffffu, ls0, 2);
        ls1 += __shfl_xor_sync(0xffffffffu, ls1, 1);
        ls1 += __shfl_xor_sync(0xffffffffu, ls1, 2);
        l0 = l0 * sc0 + ls0; m0 = mn0;
        l1 = l1 * sc1 + ls1; m1 = mn1;
#pragma unroll
        for (int nt = 0; nt < 8; nt++) {
            oacc[nt][0] *= sc0; oacc[nt][1] *= sc0;
            oacc[nt][2] *= sc1; oacc[nt][3] *= sc1;
        }

        // P -> smem (own warp's 16 rows), cvt to tf32
        {
            int r = wid * 16 + lr;
#pragma unroll
            for (int nt = 0; nt < 4; nt++) {
                int c = nt * 8 + 2 * lc;
                *(uint2*)(Ps + r * PSTR + c) =
                    make_uint2(f2tf(sacc[nt][0]), f2tf(sacc[nt][1]));
                *(uint2*)(Ps + (r + 8) * PSTR + c) =
                    make_uint2(f2tf(sacc[nt][2]), f2tf(sacc[nt][3]));
            }
        }
        __syncwarp();

        // O += P @ V  (P: 16x32, V: 32x64)
#pragma unroll
        for (int kk = 0; kk < 4; ++kk) {
            uint32_t af[4];
            int r = wid * 16 + lr;
            int c = kk * 8 + lc;
            af[0] = Ps[r * PSTR + c];
            af[1] = Ps[(r + 8) * PSTR + c];
            af[2] = Ps[r * PSTR + c + 4];
            af[3] = Ps[(r + 8) * PSTR + c + 4];
#pragma unroll
            for (int nt = 0; nt < 8; nt++) {
                uint32_t bf[2];
                int vr = kk * 8 + lc;
                bf[0] = Vs[vr * VSTR + nt * 8 + lr];
                bf[1] = Vs[(vr + 4) * VSTR + nt * 8 + lr];
                mma_tf32(oacc[nt], af, bf);
            }
        }
    }

    // finalize: write tf32-rounded ctx (feeds final GEMM directly)
    float inv0 = 1.f / l0, inv1 = 1.f / l1;
    uint32_t* Cg = (uint32_t*)(ctx + base + (size_t)qt * 128 * D_MODEL);
    int r = wid * 16 + lr;
#pragma unroll
    for (int nt = 0; nt < 8; nt++) {
        int c = nt * 8 + 2 * lc;
        *(uint2*)(Cg + (size_t)r * D_MODEL + c) =
            make_uint2(f2tf(oacc[nt][0] * inv0), f2tf(oacc[nt][1] * inv0));
        *(uint2*)(Cg + (size_t)(r + 8) * D_MODEL + c) =
            make_uint2(f2tf(oacc[nt][2] * inv1), f2tf(oacc[nt][3] * inv1));
    }
}

// ---------------------------------------------------------------------------
extern "C" void kernel_launch(void* const* d_in, const int* in_sizes, int n_in,
                              void* d_out, int out_size)
{
    const float* x  = (const float*)d_in[0];
    const float* Wq = (const float*)d_in[1];
    const float* Wk = (const float*)d_in[2];
    const float* Wv = (const float*)d_in[3];
    const float* Wo = (const float*)d_in[4];
    const float* bo = (const float*)d_in[5];
    float* out = (float*)d_out;

    float *Xb, *Wqb, *Wkb, *Wvb, *Wob, *Qb, *Kb, *Vb, *Cb;
    cudaGetSymbolAddress((void**)&Xb,  g_X);
    cudaGetSymbolAddress((void**)&Wqb, g_Wq);
    cudaGetSymbolAddress((void**)&Wkb, g_Wk);
    cudaGetSymbolAddress((void**)&Wvb, g_Wv);
    cudaGetSymbolAddress((void**)&Wob, g_Wo);
    cudaGetSymbolAddress((void**)&Qb,  g_Q);
    cudaGetSymbolAddress((void**)&Kb,  g_K);
    cudaGetSymbolAddress((void**)&Vb,  g_V);
    cudaGetSymbolAddress((void**)&Cb,  g_ctx);

    const int gsmem = GSTAGES * (A_STG + B_STG) * 4;                          // 107520 B
    const int asmem = (128 * QSTR + 128 * PSTR +
                       ASTAGES * KV * QSTR + ASTAGES * KV * VSTR) * 4;        // 107008 B
    cudaFuncSetAttribute(gemm_tf32, cudaFuncAttributeMaxDynamicSharedMemorySize, gsmem);
    cudaFuncSetAttribute(attn_tf32, cudaFuncAttributeMaxDynamicSharedMemorySize, asmem);

    // pre-round inputs to tf32 (RNA)
    const int n4x = BT * D_MODEL / 4;
    const int n4w = D_MODEL * D_MODEL / 4;
    round_tf32<<<(n4x + 255) / 256, 256>>>(x,  Xb,  n4x);
    round_tf32<<<(n4w + 255) / 256, 256>>>(Wq, Wqb, n4w);
    round_tf32<<<(n4w + 255) / 256, 256>>>(Wk, Wkb, n4w);
    round_tf32<<<(n4w + 255) / 256, 256>>>(Wv, Wvb, n4w);
    round_tf32<<<(n4w + 255) / 256, 256>>>(Wo, Wob, n4w);

    // fused QKV projections
    dim3 qkvgrid(D_MODEL / 128, BT / 128, 3);   // (8, 32, 3)
    gemm_tf32<<<qkvgrid, 256, gsmem>>>(Xb, Wqb, Wkb, Wvb, Qb, Kb, Vb, nullptr, 2);

    // attention
    dim3 agrid(SEQ / 128, NHEADS, BATCH);       // (16, 16, 2)
    attn_tf32<<<agrid, 256, asmem>>>(Qb, Kb, Vb, Cb);

    // output projection (+bias, fp32 out)
    dim3 ogrid(D_MODEL / 128, BT / 128, 1);
    gemm_tf32<<<ogrid, 256, gsmem>>>(Cb, Wob, Wob, Wob, out, out, out, bo, 0);
}

// round 5
// speedup vs baseline: 6.0691x; 2.4250x over previous
#include <cuda_runtime.h>
#include <cuda_fp16.h>
#include <cstdint>

#define D_MODEL 1024
#define NHEADS  16
#define DHEAD   64
#define BATCH   2
#define SEQ     2048
#define BT      (BATCH * SEQ)

// Scratch (allocation-free rule: __device__ globals), all fp16
__device__ __half g_X [BT * D_MODEL];
__device__ __half g_Wq[D_MODEL * D_MODEL];
__device__ __half g_Wk[D_MODEL * D_MODEL];
__device__ __half g_Wv[D_MODEL * D_MODEL];
__device__ __half g_Wo[D_MODEL * D_MODEL];
__device__ __half g_Q [BT * D_MODEL];   // pre-scaled by 1/8
__device__ __half g_K [BT * D_MODEL];
__device__ __half g_V [BT * D_MODEL];
__device__ __half g_ctx[BT * D_MODEL];

__device__ __forceinline__ uint32_t h2bits(__half2 h) { return *(uint32_t*)&h; }

__device__ __forceinline__ void mma_f16(float* c, const uint32_t* a, const uint32_t* b) {
    asm volatile(
        "mma.sync.aligned.m16n8k16.row.col.f32.f16.f16.f32 "
        "{%0,%1,%2,%3},{%4,%5,%6,%7},{%8,%9},{%0,%1,%2,%3};"
        : "+f"(c[0]), "+f"(c[1]), "+f"(c[2]), "+f"(c[3])
        : "r"(a[0]), "r"(a[1]), "r"(a[2]), "r"(a[3]), "r"(b[0]), "r"(b[1]));
}

__device__ __forceinline__ void ldsm_x4(uint32_t* r, uint32_t addr) {
    asm volatile("ldmatrix.sync.aligned.m8n8.x4.shared.b16 {%0,%1,%2,%3}, [%4];"
                 : "=r"(r[0]), "=r"(r[1]), "=r"(r[2]), "=r"(r[3]) : "r"(addr));
}
__device__ __forceinline__ void ldsm_x4t(uint32_t* r, uint32_t addr) {
    asm volatile("ldmatrix.sync.aligned.m8n8.x4.trans.shared.b16 {%0,%1,%2,%3}, [%4];"
                 : "=r"(r[0]), "=r"(r[1]), "=r"(r[2]), "=r"(r[3]) : "r"(addr));
}

__device__ __forceinline__ void cp_async16(uint32_t dst_sa, const void* src) {
    asm volatile("cp.async.ca.shared.global [%0], [%1], 16;" :: "r"(dst_sa), "l"(src));
}
__device__ __forceinline__ void cp_commit() { asm volatile("cp.async.commit_group;"); }
__device__ __forceinline__ void cp_wait1()  { asm volatile("cp.async.wait_group 1;" ::: "memory"); }
__device__ __forceinline__ void cp_wait2()  { asm volatile("cp.async.wait_group 2;" ::: "memory"); }

// ---------------------------------------------------------------------------
// fp32 -> fp16 convert (8 elements / thread, 16B stores)
// ---------------------------------------------------------------------------
__global__ __launch_bounds__(256)
void to_half(const float* __restrict__ in, __half* __restrict__ out, int n8)
{
    int i = blockIdx.x * blockDim.x + threadIdx.x;
    if (i < n8) {
        float4 a = ((const float4*)in)[2 * i];
        float4 b = ((const float4*)in)[2 * i + 1];
        uint4 u;
        u.x = h2bits(__floats2half2_rn(a.x, a.y));
        u.y = h2bits(__floats2half2_rn(a.z, a.w));
        u.z = h2bits(__floats2half2_rn(b.x, b.y));
        u.w = h2bits(__floats2half2_rn(b.z, b.w));
        ((uint4*)out)[i] = u;
    }
}

// ---------------------------------------------------------------------------
// fp16 GEMM: C = A[4096,1024] @ B[1024,1024]; inputs pre-converted fp16.
// 128x128 CTA tile, BK=32, 4-stage cp.async, 256 thr = 8 warps (4m x 2n),
// warp tile 32x64, ldmatrix fragment loads, m16n8k16 fp32-accum MMA.
// blockIdx.z selects B/C (fused QKV).
// ---------------------------------------------------------------------------
#define ASTRH 40      // A smem stride (halves): 80B -> ldmatrix conflict-free
#define BSTRH 136     // B smem stride (halves): 272B -> conflict-free
#define KTILE 32
#define GSTAGES 4
#define A_STG_H (128 * ASTRH)   // 5120 halves
#define B_STG_H (KTILE * BSTRH) // 4352 halves

__global__ __launch_bounds__(256, 2)
void gemm_f16(const __half* __restrict__ A,
              const __half* __restrict__ B0, const __half* __restrict__ B1,
              const __half* __restrict__ B2,
              __half* __restrict__ H0, __half* __restrict__ H1, __half* __restrict__ H2,
              float* __restrict__ F, const float* __restrict__ bias,
              int fp32_out, float scale0)
{
    extern __shared__ __half smh[];
    __half* As = smh;                       // [GSTAGES][A_STG_H]
    __half* Bs = smh + GSTAGES * A_STG_H;   // [GSTAGES][B_STG_H]

    const int z = blockIdx.z;
    const __half* B = (z == 0) ? B0 : (z == 1) ? B1 : B2;
    __half*       H = (z == 0) ? H0 : (z == 1) ? H1 : H2;
    const float scale = (z == 0) ? scale0 : 1.0f;

    const int tid  = threadIdx.x;
    const int lane = tid & 31;
    const int wid  = tid >> 5;
    const int wm   = wid & 3;
    const int wn   = wid >> 2;
    const int lr   = lane >> 2;
    const int lc   = lane & 3;
    const int row0 = blockIdx.y * 128;
    const int col0 = blockIdx.x * 128;

    // cp.async mappings
    const int arow = tid >> 1;            // 0..127
    const int achk = (tid & 1) * 2;       // chunks {0,1} or {2,3} (16B = 8 halves)
    const int brow = tid >> 3;            // 0..31
    const int bchk = (tid & 7) * 2;       // 2 of 16 chunks per row

    const __half* Ag = A + (size_t)(row0 + arow) * D_MODEL + achk * 8;
    const __half* Bg = B + (size_t)brow * D_MODEL + col0 + bchk * 8;
    const uint32_t saA = (uint32_t)__cvta_generic_to_shared(As);
    const uint32_t saB = (uint32_t)__cvta_generic_to_shared(Bs);
    const uint32_t dA0 = saA + (arow * ASTRH + achk * 8) * 2;
    const uint32_t dB0 = saB + (brow * BSTRH + bchk * 8) * 2;

    auto load_tile = [&](int t) {
        int s = t % GSTAGES;
        const __half* a = Ag + t * KTILE;
        const __half* b = Bg + (size_t)t * KTILE * D_MODEL;
        uint32_t da = dA0 + s * A_STG_H * 2;
        uint32_t db = dB0 + s * B_STG_H * 2;
        cp_async16(da,      a);
        cp_async16(da + 16, a + 8);
        cp_async16(db,      b);
        cp_async16(db + 16, b + 8);
    };

    load_tile(0); cp_commit();
    load_tile(1); cp_commit();
    load_tile(2); cp_commit();

    float acc[2][8][4];
#pragma unroll
    for (int mt = 0; mt < 2; mt++)
#pragma unroll
        for (int nt = 0; nt < 8; nt++)
#pragma unroll
            for (int j = 0; j < 4; j++) acc[mt][nt][j] = 0.f;

    // ldmatrix per-thread bases
    const int lrowA = wm * 32 + (lane & 15);      // + mt*16
    const int lcolA = (lane >> 4) * 8;            // + kk*16
    const int lkB   = (lane & 15);                // + kk*16
    const int lnB   = wn * 64 + (lane >> 4) * 8;  // + ntp*16

    const int kIters = D_MODEL / KTILE;   // 32
    for (int it = 0; it < kIters; ++it) {
        cp_wait2();
        __syncthreads();
        if (it + 3 < kIters) load_tile(it + 3);
        cp_commit();

        const uint32_t bA = saA + (it % GSTAGES) * A_STG_H * 2;
        const uint32_t bB = saB + (it % GSTAGES) * B_STG_H * 2;

#pragma unroll
        for (int kk = 0; kk < 2; ++kk) {
            uint32_t af[2][4];
            ldsm_x4(af[0], bA + ((lrowA) * ASTRH + lcolA + kk * 16) * 2);
            ldsm_x4(af[1], bA + ((lrowA + 16) * ASTRH + lcolA + kk * 16) * 2);
            uint32_t bf[4][4];
#pragma unroll
            for (int ntp = 0; ntp < 4; ntp++)
                ldsm_x4t(bf[ntp], bB + ((lkB + kk * 16) * BSTRH + lnB + ntp * 16) * 2);
#pragma unroll
            for (int mt = 0; mt < 2; mt++)
#pragma unroll
                for (int nt = 0; nt < 8; nt++)
                    mma_f16(acc[mt][nt], af[mt], &bf[nt >> 1][(nt & 1) * 2]);
        }
    }

    // epilogue
#pragma unroll
    for (int mt = 0; mt < 2; mt++) {
        int r = row0 + wm * 32 + mt * 16 + lr;
#pragma unroll
        for (int nt = 0; nt < 8; nt++) {
            int c = col0 + wn * 64 + nt * 8 + 2 * lc;
            float* v = acc[mt][nt];
            if (fp32_out) {
                float bx = bias[c], by = bias[c + 1];
                *(float2*)(F + (size_t)r * D_MODEL + c) = make_float2(v[0] + bx, v[1] + by);
                *(float2*)(F + (size_t)(r + 8) * D_MODEL + c) = make_float2(v[2] + bx, v[3] + by);
            } else {
                *(uint32_t*)(H + (size_t)r * D_MODEL + c) =
                    h2bits(__floats2half2_rn(v[0] * scale, v[1] * scale));
                *(uint32_t*)(H + (size_t)(r + 8) * D_MODEL + c) =
                    h2bits(__floats2half2_rn(v[2] * scale, v[3] * scale));
            }
        }
    }
}

// ---------------------------------------------------------------------------
// Causal flash attention, fp16 mma + fp32 online softmax.
// CTA = 128 q rows (8 warps x 16); KV tiles of 64 keys, 3-stage cp.async.
// P stays in registers (S-accum layout == A-fragment layout for m16n8k16).
// ---------------------------------------------------------------------------
#define QSTRH 72     // 144B stride -> ldmatrix conflict-free
#define KV    64
#define ASTAGES 3
#define KV_STG_H (KV * QSTRH)

__global__ __launch_bounds__(256, 2)
void attn_f16(const __half* __restrict__ Q, const __half* __restrict__ K,
              const __half* __restrict__ V, __half* __restrict__ ctx)
{
    extern __shared__ __half smh[];
    __half* Qs = smh;                         // [128][QSTRH]
    __half* Kd = Qs + 128 * QSTRH;            // [3][KV][QSTRH]
    __half* Vd = Kd + ASTAGES * KV_STG_H;     // [3][KV][QSTRH]

    const int tid  = threadIdx.x;
    const int lane = tid & 31;
    const int wid  = tid >> 5;
    const int lr   = lane >> 2;
    const int lc   = lane & 3;
    const int qt   = gridDim.x - 1 - blockIdx.x;  // heavy tiles first
    const int h    = blockIdx.y;
    const int b    = blockIdx.z;

    const size_t base = (size_t)(b * SEQ) * D_MODEL + h * DHEAD;
    const __half* Qg  = Q + base + (size_t)qt * 128 * D_MODEL;
    const __half* Kg0 = K + base;
    const __half* Vg0 = V + base;

    const uint32_t saQ = (uint32_t)__cvta_generic_to_shared(Qs);
    const uint32_t saK = (uint32_t)__cvta_generic_to_shared(Kd);
    const uint32_t saV = (uint32_t)__cvta_generic_to_shared(Vd);

    // KV cp.async: row = tid>>2 (0..63), two 16B chunks at (tid&3)*2
    const int krow = tid >> 2;
    const int kchk = (tid & 3) * 2;

    auto copy_kv = [&](int t) {
        int s = t % ASTAGES;
        const __half* Kg = Kg0 + ((size_t)t * KV + krow) * D_MODEL + kchk * 8;
        const __half* Vg = Vg0 + ((size_t)t * KV + krow) * D_MODEL + kchk * 8;
        uint32_t kd = saK + (s * KV_STG_H + krow * QSTRH + kchk * 8) * 2;
        uint32_t vd = saV + (s * KV_STG_H + krow * QSTRH + kchk * 8) * 2;
        cp_async16(kd,      Kg);
        cp_async16(kd + 16, Kg + 8);
        cp_async16(vd,      Vg);
        cp_async16(vd + 16, Vg + 8);
    };

    // Load Q tile: 128 rows x 8 chunks (16B)
    for (int i = tid; i < 128 * 8; i += 256) {
        int row = i >> 3, ch = i & 7;
        *(uint4*)&Qs[row * QSTRH + ch * 8] =
            *(const uint4*)(Qg + (size_t)row * D_MODEL + ch * 8);
    }

    const int nkt = 2 * qt + 2;
    copy_kv(0); cp_commit();
    copy_kv(1); cp_commit();

    float oacc[8][4];
#pragma unroll
    for (int nt = 0; nt < 8; nt++)
#pragma unroll
        for (int j = 0; j < 4; j++) oacc[nt][j] = 0.f;
    float m0 = -1e30f, m1 = -1e30f, l0 = 0.f, l1 = 0.f;

    const int rg0 = qt * 128 + wid * 16 + lr;

    // ldmatrix bases
    const int qrow = wid * 16 + (lane & 15);
    const int qcol = (lane >> 4) * 8;                       // + kk*16
    const int krow_f = (lane >> 4) * 8 + (lane & 7);        // + ntp*16  (key idx)
    const int kcol_f = ((lane >> 3) & 1) * 8;               // + kk*16   (d idx)
    const int vrow_f = (lane & 15);                         // + j*16    (key idx)
    const int vcol_f = (lane >> 4) * 8;                     // + ntp*16  (d idx)

    for (int kt = 0; kt < nkt; ++kt) {
        cp_wait1();
        __syncthreads();
        if (kt + 2 < nkt) copy_kv(kt + 2);
        cp_commit();

        const uint32_t bK = saK + (kt % ASTAGES) * KV_STG_H * 2;
        const uint32_t bV = saV + (kt % ASTAGES) * KV_STG_H * 2;

        // S = Q @ K^T : 16 x 64 per warp
        float sacc[8][4];
#pragma unroll
        for (int nt = 0; nt < 8; nt++)
#pragma unroll
            for (int j = 0; j < 4; j++) sacc[nt][j] = 0.f;

#pragma unroll
        for (int kk = 0; kk < 4; ++kk) {          // d blocks of 16
            uint32_t qf[4];
            ldsm_x4(qf, saQ + (qrow * QSTRH + qcol + kk * 16) * 2);
#pragma unroll
            for (int ntp = 0; ntp < 4; ntp++) {   // key blocks of 16
                uint32_t kf[4];
                ldsm_x4(kf, bK + ((krow_f + ntp * 16) * QSTRH + kcol_f + kk * 16) * 2);
                mma_f16(sacc[2 * ntp],     qf, &kf[0]);
                mma_f16(sacc[2 * ntp + 1], qf, &kf[2]);
            }
        }

        // causal mask near the diagonal (last 2 tiles)
        if (kt >= 2 * qt) {
            int cbase = kt * KV;
#pragma unroll
            for (int nt = 0; nt < 8; nt++) {
                int cg = cbase + nt * 8 + 2 * lc;
                if (cg     > rg0)     sacc[nt][0] = -1e30f;
                if (cg + 1 > rg0)     sacc[nt][1] = -1e30f;
                if (cg     > rg0 + 8) sacc[nt][2] = -1e30f;
                if (cg + 1 > rg0 + 8) sacc[nt][3] = -1e30f;
            }
        }

        // online softmax
        float rm0 = -1e30f, rm1 = -1e30f;
#pragma unroll
        for (int nt = 0; nt < 8; nt++) {
            rm0 = fmaxf(rm0, fmaxf(sacc[nt][0], sacc[nt][1]));
            rm1 = fmaxf(rm1, fmaxf(sacc[nt][2], sacc[nt][3]));
        }
        rm0 = fmaxf(rm0, __shfl_xor_sync(0xffffffffu, rm0, 1));
        rm0 = fmaxf(rm0, __shfl_xor_sync(0xffffffffu, rm0, 2));
        rm1 = fmaxf(rm1, __shfl_xor_sync(0xffffffffu, rm1, 1));
        rm1 = fmaxf(rm1, __shfl_xor_sync(0xffffffffu, rm1, 2));

        float mn0 = fmaxf(m0, rm0), mn1 = fmaxf(m1, rm1);
        float sc0 = __expf(m0 - mn0), sc1 = __expf(m1 - mn1);
        float ls0 = 0.f, ls1 = 0.f;
#pragma unroll
        for (int nt = 0; nt < 8; nt++) {
            sacc[nt][0] = __expf(sacc[nt][0] - mn0);
            sacc[nt][1] = __expf(sacc[nt][1] - mn0);
            sacc[nt][2] = __expf(sacc[nt][2] - mn1);
            sacc[nt][3] = __expf(sacc[nt][3] - mn1);
            ls0 += sacc[nt][0] + sacc[nt][1];
            ls1 += sacc[nt][2] + sacc[nt][3];
        }
        ls0 += __shfl_xor_sync(0xffffffffu, ls0, 1);
        ls0 += __shfl_xor_sync(0xffffffffu, ls0, 2);
        ls1 += __shfl_xor_sync(0xffffffffu, ls1, 1);
        ls1 += __shfl_xor_sync(0xffffffffu, ls1, 2);
        l0 = l0 * sc0 + ls0; m0 = mn0;
        l1 = l1 * sc1 + ls1; m1 = mn1;
#pragma unroll
        for (int nt = 0; nt < 8; nt++) {
            oacc[nt][0] *= sc0; oacc[nt][1] *= sc0;
            oacc[nt][2] *= sc1; oacc[nt][3] *= sc1;
        }

        // O += P @ V ; P A-fragments come straight from sacc registers
#pragma unroll
        for (int j = 0; j < 4; ++j) {             // key blocks of 16
            uint32_t pf[4];
            pf[0] = h2bits(__floats2half2_rn(sacc[2 * j][0],     sacc[2 * j][1]));
            pf[1] = h2bits(__floats2half2_rn(sacc[2 * j][2],     sacc[2 * j][3]));
            pf[2] = h2bits(__floats2half2_rn(sacc[2 * j + 1][0], sacc[2 * j + 1][1]));
            pf[3] = h2bits(__floats2half2_rn(sacc[2 * j + 1][2], sacc[2 * j + 1][3]));
#pragma unroll
            for (int ntp = 0; ntp < 4; ntp++) {   // d blocks of 16
                uint32_t vf[4];
                ldsm_x4t(vf, bV + ((vrow_f + j * 16) * QSTRH + vcol_f + ntp * 16) * 2);
                mma_f16(oacc[2 * ntp],     pf, &vf[0]);
                mma_f16(oacc[2 * ntp + 1], pf, &vf[2]);
            }
        }
    }

    // finalize: write fp16 ctx
    float inv0 = 1.f / l0, inv1 = 1.f / l1;
    __half* Cg = ctx + base + (size_t)qt * 128 * D_MODEL;
    int r = wid * 16 + lr;
#pragma unroll
    for (int nt = 0; nt < 8; nt++) {
        int c = nt * 8 + 2 * lc;
        *(uint32_t*)(Cg + (size_t)r * D_MODEL + c) =
            h2bits(__floats2half2_rn(oacc[nt][0] * inv0, oacc[nt][1] * inv0));
        *(uint32_t*)(Cg + (size_t)(r + 8) * D_MODEL + c) =
            h2bits(__floats2half2_rn(oacc[nt][2] * inv1, oacc[nt][3] * inv1));
    }
}

// ---------------------------------------------------------------------------
extern "C" void kernel_launch(void* const* d_in, const int* in_sizes, int n_in,
                              void* d_out, int out_size)
{
    const float* x  = (const float*)d_in[0];
    const float* Wq = (const float*)d_in[1];
    const float* Wk = (const float*)d_in[2];
    const float* Wv = (const float*)d_in[3];
    const float* Wo = (const float*)d_in[4];
    const float* bo = (const float*)d_in[5];
    float* out = (float*)d_out;

    __half *Xb, *Wqb, *Wkb, *Wvb, *Wob, *Qb, *Kb, *Vb, *Cb;
    cudaGetSymbolAddress((void**)&Xb,  g_X);
    cudaGetSymbolAddress((void**)&Wqb, g_Wq);
    cudaGetSymbolAddress((void**)&Wkb, g_Wk);
    cudaGetSymbolAddress((void**)&Wvb, g_Wv);
    cudaGetSymbolAddress((void**)&Wob, g_Wo);
    cudaGetSymbolAddress((void**)&Qb,  g_Q);
    cudaGetSymbolAddress((void**)&Kb,  g_K);
    cudaGetSymbolAddress((void**)&Vb,  g_V);
    cudaGetSymbolAddress((void**)&Cb,  g_ctx);

    const int gsmem = GSTAGES * (A_STG_H + B_STG_H) * 2;                // 75776 B
    const int asmem = (128 * QSTRH + 2 * ASTAGES * KV_STG_H) * 2;       // 73728 B
    cudaFuncSetAttribute(gemm_f16, cudaFuncAttributeMaxDynamicSharedMemorySize, gsmem);
    cudaFuncSetAttribute(attn_f16, cudaFuncAttributeMaxDynamicSharedMemorySize, asmem);

    // fp32 -> fp16 conversions
    const int n8x = BT * D_MODEL / 8;        // 524288
    const int n8w = D_MODEL * D_MODEL / 8;   // 131072
    to_half<<<(n8x + 255) / 256, 256>>>(x,  Xb,  n8x);
    to_half<<<(n8w + 255) / 256, 256>>>(Wq, Wqb, n8w);
    to_half<<<(n8w + 255) / 256, 256>>>(Wk, Wkb, n8w);
    to_half<<<(n8w + 255) / 256, 256>>>(Wv, Wvb, n8w);
    to_half<<<(n8w + 255) / 256, 256>>>(Wo, Wob, n8w);

    // fused QKV projections (Q gets 1/8 pre-scale)
    dim3 qkvgrid(D_MODEL / 128, BT / 128, 3);   // (8, 32, 3)
    gemm_f16<<<qkvgrid, 256, gsmem>>>(Xb, Wqb, Wkb, Wvb, Qb, Kb, Vb,
                                      nullptr, nullptr, 0, 0.125f);

    // attention
    dim3 agrid(SEQ / 128, NHEADS, BATCH);       // (16, 16, 2)
    attn_f16<<<agrid, 256, asmem>>>(Qb, Kb, Vb, Cb);

    // output projection (+bias, fp32 out)
    dim3 ogrid(D_MODEL / 128, BT / 128, 1);
    gemm_f16<<<ogrid, 256, gsmem>>>(Cb, Wob, Wob, Wob, nullptr, nullptr, nullptr,
                                    out, bo, 1, 1.0f);
}

// round 7
// speedup vs baseline: 6.3827x; 1.0517x over previous
#include <cuda_runtime.h>
#include <cuda_fp16.h>
#include <cstdint>

#define D_MODEL 1024
#define NHEADS  16
#define DHEAD   64
#define BATCH   2
#define SEQ     2048
#define BT      (BATCH * SEQ)

// Scratch (allocation-free rule: __device__ globals), all fp16
__device__ __half g_X [BT * D_MODEL];
__device__ __half g_Wq[D_MODEL * D_MODEL];
__device__ __half g_Wk[D_MODEL * D_MODEL];
__device__ __half g_Wv[D_MODEL * D_MODEL];
__device__ __half g_Wo[D_MODEL * D_MODEL];
__device__ __half g_Q [BT * D_MODEL];   // pre-scaled by 0.125*log2(e)
__device__ __half g_K [BT * D_MODEL];
__device__ __half g_V [BT * D_MODEL];
__device__ __half g_ctx[BT * D_MODEL];

__device__ __forceinline__ uint32_t h2bits(__half2 h) { return *(uint32_t*)&h; }

__device__ __forceinline__ void mma_f16(float* c, const uint32_t* a, const uint32_t* b) {
    asm volatile(
        "mma.sync.aligned.m16n8k16.row.col.f32.f16.f16.f32 "
        "{%0,%1,%2,%3},{%4,%5,%6,%7},{%8,%9},{%0,%1,%2,%3};"
        : "+f"(c[0]), "+f"(c[1]), "+f"(c[2]), "+f"(c[3])
        : "r"(a[0]), "r"(a[1]), "r"(a[2]), "r"(a[3]), "r"(b[0]), "r"(b[1]));
}

__device__ __forceinline__ void ldsm_x4(uint32_t* r, uint32_t addr) {
    asm volatile("ldmatrix.sync.aligned.m8n8.x4.shared.b16 {%0,%1,%2,%3}, [%4];"
                 : "=r"(r[0]), "=r"(r[1]), "=r"(r[2]), "=r"(r[3]) : "r"(addr));
}
__device__ __forceinline__ void ldsm_x4t(uint32_t* r, uint32_t addr) {
    asm volatile("ldmatrix.sync.aligned.m8n8.x4.trans.shared.b16 {%0,%1,%2,%3}, [%4];"
                 : "=r"(r[0]), "=r"(r[1]), "=r"(r[2]), "=r"(r[3]) : "r"(addr));
}

__device__ __forceinline__ void cp_async16(uint32_t dst_sa, const void* src) {
    asm volatile("cp.async.ca.shared.global [%0], [%1], 16;" :: "r"(dst_sa), "l"(src));
}
__device__ __forceinline__ void cp_commit() { asm volatile("cp.async.commit_group;"); }
__device__ __forceinline__ void cp_wait1()  { asm volatile("cp.async.wait_group 1;" ::: "memory"); }
__device__ __forceinline__ void cp_wait2()  { asm volatile("cp.async.wait_group 2;" ::: "memory"); }

// ---------------------------------------------------------------------------
// fp32 -> fp16 convert (8 elements / thread, 16B stores)
// ---------------------------------------------------------------------------
__global__ __launch_bounds__(256)
void to_half(const float* __restrict__ in, __half* __restrict__ out, int n8)
{
    int i = blockIdx.x * blockDim.x + threadIdx.x;
    if (i < n8) {
        float4 a = ((const float4*)in)[2 * i];
        float4 b = ((const float4*)in)[2 * i + 1];
        uint4 u;
        u.x = h2bits(__floats2half2_rn(a.x, a.y));
        u.y = h2bits(__floats2half2_rn(a.z, a.w));
        u.z = h2bits(__floats2half2_rn(b.x, b.y));
        u.w = h2bits(__floats2half2_rn(b.z, b.w));
        ((uint4*)out)[i] = u;
    }
}

// ---------------------------------------------------------------------------
// fp16 GEMM (identical to the verified R4 kernel):
// C = A[4096,1024] @ B[1024,1024]; 128x128 CTA tile, BK=32, 4-stage cp.async,
// 256 thr = 8 warps (4m x 2n), warp tile 32x64, ldmatrix + m16n8k16.
// blockIdx.z selects B/C (fused QKV).
// ---------------------------------------------------------------------------
#define ASTRH 40
#define BSTRH 136
#define KTILE 32
#define GSTAGES 4
#define A_STG_H (128 * ASTRH)
#define B_STG_H (KTILE * BSTRH)

__global__ __launch_bounds__(256, 2)
void gemm_f16(const __half* __restrict__ A,
              const __half* __restrict__ B0, const __half* __restrict__ B1,
              const __half* __restrict__ B2,
              __half* __restrict__ H0, __half* __restrict__ H1, __half* __restrict__ H2,
              float* __restrict__ F, const float* __restrict__ bias,
              int fp32_out, float scale0)
{
    extern __shared__ __half smh[];
    __half* As = smh;
    __half* Bs = smh + GSTAGES * A_STG_H;

    const int z = blockIdx.z;
    const __half* B = (z == 0) ? B0 : (z == 1) ? B1 : B2;
    __half*       H = (z == 0) ? H0 : (z == 1) ? H1 : H2;
    const float scale = (z == 0) ? scale0 : 1.0f;

    const int tid  = threadIdx.x;
    const int lane = tid & 31;
    const int wid  = tid >> 5;
    const int wm   = wid & 3;
    const int wn   = wid >> 2;
    const int lr   = lane >> 2;
    const int lc   = lane & 3;
    const int row0 = blockIdx.y * 128;
    const int col0 = blockIdx.x * 128;

    const int arow = tid >> 1;
    const int achk = (tid & 1) * 2;
    const int brow = tid >> 3;
    const int bchk = (tid & 7) * 2;

    const __half* Ag = A + (size_t)(row0 + arow) * D_MODEL + achk * 8;
    const __half* Bg = B + (size_t)brow * D_MODEL + col0 + bchk * 8;
    const uint32_t saA = (uint32_t)__cvta_generic_to_shared(As);
    const uint32_t saB = (uint32_t)__cvta_generic_to_shared(Bs);
    const uint32_t dA0 = saA + (arow * ASTRH + achk * 8) * 2;
    const uint32_t dB0 = saB + (brow * BSTRH + bchk * 8) * 2;

    auto load_tile = [&](int t) {
        int s = t % GSTAGES;
        const __half* a = Ag + t * KTILE;
        const __half* b = Bg + (size_t)t * KTILE * D_MODEL;
        uint32_t da = dA0 + s * A_STG_H * 2;
        uint32_t db = dB0 + s * B_STG_H * 2;
        cp_async16(da,      a);
        cp_async16(da + 16, a + 8);
        cp_async16(db,      b);
        cp_async16(db + 16, b + 8);
    };

    load_tile(0); cp_commit();
    load_tile(1); cp_commit();
    load_tile(2); cp_commit();

    float acc[2][8][4];
#pragma unroll
    for (int mt = 0; mt < 2; mt++)
#pragma unroll
        for (int nt = 0; nt < 8; nt++)
#pragma unroll
            for (int j = 0; j < 4; j++) acc[mt][nt][j] = 0.f;

    const int lrowA = wm * 32 + (lane & 15);
    const int lcolA = (lane >> 4) * 8;
    const int lkB   = (lane & 15);
    const int lnB   = wn * 64 + (lane >> 4) * 8;

    const int kIters = D_MODEL / KTILE;   // 32
    for (int it = 0; it < kIters; ++it) {
        cp_wait2();
        __syncthreads();
        if (it + 3 < kIters) load_tile(it + 3);
        cp_commit();

        const uint32_t bA = saA + (it % GSTAGES) * A_STG_H * 2;
        const uint32_t bB = saB + (it % GSTAGES) * B_STG_H * 2;

#pragma unroll
        for (int kk = 0; kk < 2; ++kk) {
            uint32_t af[2][4];
            ldsm_x4(af[0], bA + ((lrowA) * ASTRH + lcolA + kk * 16) * 2);
            ldsm_x4(af[1], bA + ((lrowA + 16) * ASTRH + lcolA + kk * 16) * 2);
            uint32_t bf[4][4];
#pragma unroll
            for (int ntp = 0; ntp < 4; ntp++)
                ldsm_x4t(bf[ntp], bB + ((lkB + kk * 16) * BSTRH + lnB + ntp * 16) * 2);
#pragma unroll
            for (int mt = 0; mt < 2; mt++)
#pragma unroll
                for (int nt = 0; nt < 8; nt++)
                    mma_f16(acc[mt][nt], af[mt], &bf[nt >> 1][(nt & 1) * 2]);
        }
    }

#pragma unroll
    for (int mt = 0; mt < 2; mt++) {
        int r = row0 + wm * 32 + mt * 16 + lr;
#pragma unroll
        for (int nt = 0; nt < 8; nt++) {
            int c = col0 + wn * 64 + nt * 8 + 2 * lc;
            float* v = acc[mt][nt];
            if (fp32_out) {
                float bx = bias[c], by = bias[c + 1];
                *(float2*)(F + (size_t)r * D_MODEL + c) = make_float2(v[0] + bx, v[1] + by);
                *(float2*)(F + (size_t)(r + 8) * D_MODEL + c) = make_float2(v[2] + bx, v[3] + by);
            } else {
                *(uint32_t*)(H + (size_t)r * D_MODEL + c) =
                    h2bits(__floats2half2_rn(v[0] * scale, v[1] * scale));
                *(uint32_t*)(H + (size_t)(r + 8) * D_MODEL + c) =
                    h2bits(__floats2half2_rn(v[2] * scale, v[3] * scale));
            }
        }
    }
}

// ---------------------------------------------------------------------------
// Causal flash attention, fp16 mma + base-2 online softmax.
// CTA = 128 q rows (8 warps x 16); KV tiles of 64 keys, 3-stage cp.async.
// Q fragments hoisted out of the KV loop; P stays in registers;
// fully-masked warps skip the last diagonal tile.
// Q arrives pre-scaled by 0.125*log2(e) -> softmax uses exp2.
// ---------------------------------------------------------------------------
#define QSTRH 72
#define KV    64
#define ASTAGES 3
#define KV_STG_H (KV * QSTRH)

__global__ __launch_bounds__(256, 2)
void attn_f16(const __half* __restrict__ Q, const __half* __restrict__ K,
              const __half* __restrict__ V, __half* __restrict__ ctx)
{
    extern __shared__ __half smh[];
    __half* Qs = smh;                         // [128][QSTRH]
    __half* Kd = Qs + 128 * QSTRH;            // [3][KV][QSTRH]
    __half* Vd = Kd + ASTAGES * KV_STG_H;     // [3][KV][QSTRH]

    const int tid  = threadIdx.x;
    const int lane = tid & 31;
    const int wid  = tid >> 5;
    const int lr   = lane >> 2;
    const int lc   = lane & 3;
    const int qt   = gridDim.x - 1 - blockIdx.x;  // heavy tiles first
    const int h    = blockIdx.y;
    const int b    = blockIdx.z;

    const size_t base = (size_t)(b * SEQ) * D_MODEL + h * DHEAD;
    const __half* Qg  = Q + base + (size_t)qt * 128 * D_MODEL;
    const __half* Kg0 = K + base;
    const __half* Vg0 = V + base;

    const uint32_t saQ = (uint32_t)__cvta_generic_to_shared(Qs);
    const uint32_t saK = (uint32_t)__cvta_generic_to_shared(Kd);
    const uint32_t saV = (uint32_t)__cvta_generic_to_shared(Vd);

    const int krow = tid >> 2;
    const int kchk = (tid & 3) * 2;

    auto copy_kv = [&](int t) {
        int s = t % ASTAGES;
        const __half* Kg = Kg0 + ((size_t)t * KV + krow) * D_MODEL + kchk * 8;
        const __half* Vg = Vg0 + ((size_t)t * KV + krow) * D_MODEL + kchk * 8;
        uint32_t kd = saK + (s * KV_STG_H + krow * QSTRH + kchk * 8) * 2;
        uint32_t vd = saV + (s * KV_STG_H + krow * QSTRH + kchk * 8) * 2;
        cp_async16(kd,      Kg);
        cp_async16(kd + 16, Kg + 8);
        cp_async16(vd,      Vg);
        cp_async16(vd + 16, Vg + 8);
    };

    // Load Q tile
    for (int i = tid; i < 128 * 8; i += 256) {
        int row = i >> 3, ch = i & 7;
        *(uint4*)&Qs[row * QSTRH + ch * 8] =
            *(const uint4*)(Qg + (size_t)row * D_MODEL + ch * 8);
    }

    const int nkt = 2 * qt + 2;
    copy_kv(0); cp_commit();
    copy_kv(1); cp_commit();

    // Hoist Q fragments (loop-invariant): sync Q smem writes, then ldmatrix once.
    __syncthreads();
    const int qrow = wid * 16 + (lane & 15);
    const int qcol = (lane >> 4) * 8;
    uint32_t qfr[4][4];
#pragma unroll
    for (int kk = 0; kk < 4; kk++)
        ldsm_x4(qfr[kk], saQ + (qrow * QSTRH + qcol + kk * 16) * 2);

    float oacc[8][4];
#pragma unroll
    for (int nt = 0; nt < 8; nt++)
#pragma unroll
        for (int j = 0; j < 4; j++) oacc[nt][j] = 0.f;
    float m0 = -1e30f, m1 = -1e30f, l0 = 0.f, l1 = 0.f;

    const int rg0 = qt * 128 + wid * 16 + lr;

    const int krow_f = (lane >> 4) * 8 + (lane & 7);
    const int kcol_f = ((lane >> 3) & 1) * 8;
    const int vrow_f = (lane & 15);
    const int vcol_f = (lane >> 4) * 8;

    for (int kt = 0; kt < nkt; ++kt) {
        cp_wait1();
        __syncthreads();
        if (kt + 2 < nkt) copy_kv(kt + 2);
        cp_commit();

        // last diagonal tile: warps 0-3 (rows qt*128..qt*128+63) are entirely
        // below all keys [qt*128+64, qt*128+128) -> fully masked, skip.
        if (kt == nkt - 1 && wid < 4) continue;

        const uint32_t bK = saK + (kt % ASTAGES) * KV_STG_H * 2;
        const uint32_t bV = saV + (kt % ASTAGES) * KV_STG_H * 2;

        // S = Q @ K^T : 16 x 64 per warp (scores already in log2 units)
        float sacc[8][4];
#pragma unroll
        for (int nt = 0; nt < 8; nt++)
#pragma unroll
            for (int j = 0; j < 4; j++) sacc[nt][j] = 0.f;

#pragma unroll
        for (int kk = 0; kk < 4; ++kk) {
#pragma unroll
            for (int ntp = 0; ntp < 4; ntp++) {
                uint32_t kf[4];
                ldsm_x4(kf, bK + ((krow_f + ntp * 16) * QSTRH + kcol_f + kk * 16) * 2);
                mma_f16(sacc[2 * ntp],     qfr[kk], &kf[0]);
                mma_f16(sacc[2 * ntp + 1], qfr[kk], &kf[2]);
            }
        }

        // causal mask near the diagonal (last 2 tiles)
        if (kt >= 2 * qt) {
            int cbase = kt * KV;
#pragma unroll
            for (int nt = 0; nt < 8; nt++) {
                int cg = cbase + nt * 8 + 2 * lc;
                if (cg     > rg0)     sacc[nt][0] = -1e30f;
                if (cg + 1 > rg0)     sacc[nt][1] = -1e30f;
                if (cg     > rg0 + 8) sacc[nt][2] = -1e30f;
                if (cg + 1 > rg0 + 8) sacc[nt][3] = -1e30f;
            }
        }

        // online softmax (base-2)
        float rm0 = -1e30f, rm1 = -1e30f;
#pragma unroll
        for (int nt = 0; nt < 8; nt++) {
            rm0 = fmaxf(rm0, fmaxf(sacc[nt][0], sacc[nt][1]));
            rm1 = fmaxf(rm1, fmaxf(sacc[nt][2], sacc[nt][3]));
        }
        rm0 = fmaxf(rm0, __shfl_xor_sync(0xffffffffu, rm0, 1));
        rm0 = fmaxf(rm0, __shfl_xor_sync(0xffffffffu, rm0, 2));
        rm1 = fmaxf(rm1, __shfl_xor_sync(0xffffffffu, rm1, 1));
        rm1 = fmaxf(rm1, __shfl_xor_sync(0xffffffffu, rm1, 2));

        float mn0 = fmaxf(m0, rm0), mn1 = fmaxf(m1, rm1);
        float sc0 = exp2f(m0 - mn0), sc1 = exp2f(m1 - mn1);
        float ls0 = 0.f, ls1 = 0.f;
#pragma unroll
        for (int nt = 0; nt < 8; nt++) {
            sacc[nt][0] = exp2f(sacc[nt][0] - mn0);
            sacc[nt][1] = exp2f(sacc[nt][1] - mn0);
            sacc[nt][2] = exp2f(sacc[nt][2] - mn1);
            sacc[nt][3] = exp2f(sacc[nt][3] - mn1);
            ls0 += sacc[nt][0] + sacc[nt][1];
            ls1 += sacc[nt][2] + sacc[nt][3];
        }
        ls0 += __shfl_xor_sync(0xffffffffu, ls0, 1);
        ls0 += __shfl_xor_sync(0xffffffffu, ls0, 2);
        ls1 += __shfl_xor_sync(0xffffffffu, ls1, 1);
        ls1 += __shfl_xor_sync(0xffffffffu, ls1, 2);
        l0 = l0 * sc0 + ls0; m0 = mn0;
        l1 = l1 * sc1 + ls1; m1 = mn1;
#pragma unroll
        for (int nt = 0; nt < 8; nt++) {
            oacc[nt][0] *= sc0; oacc[nt][1] *= sc0;
            oacc[nt][2] *= sc1; oacc[nt][3] *= sc1;
        }

        // O += P @ V ; P A-fragments straight from sacc registers
#pragma unroll
        for (int j = 0; j < 4; ++j) {
            uint32_t pf[4];
            pf[0] = h2bits(__floats2half2_rn(sacc[2 * j][0],     sacc[2 * j][1]));
            pf[1] = h2bits(__floats2half2_rn(sacc[2 * j][2],     sacc[2 * j][3]));
            pf[2] = h2bits(__floats2half2_rn(sacc[2 * j + 1][0], sacc[2 * j + 1][1]));
            pf[3] = h2bits(__floats2half2_rn(sacc[2 * j + 1][2], sacc[2 * j + 1][3]));
#pragma unroll
            for (int ntp = 0; ntp < 4; ntp++) {
                uint32_t vf[4];
                ldsm_x4t(vf, bV + ((vrow_f + j * 16) * QSTRH + vcol_f + ntp * 16) * 2);
                mma_f16(oacc[2 * ntp],     pf, &vf[0]);
                mma_f16(oacc[2 * ntp + 1], pf, &vf[2]);
            }
        }
    }

    // finalize: write fp16 ctx
    float inv0 = 1.f / l0, inv1 = 1.f / l1;
    __half* Cg = ctx + base + (size_t)qt * 128 * D_MODEL;
    int r = wid * 16 + lr;
#pragma unroll
    for (int nt = 0; nt < 8; nt++) {
        int c = nt * 8 + 2 * lc;
        *(uint32_t*)(Cg + (size_t)r * D_MODEL + c) =
            h2bits(__floats2half2_rn(oacc[nt][0] * inv0, oacc[nt][1] * inv0));
        *(uint32_t*)(Cg + (size_t)(r + 8) * D_MODEL + c) =
            h2bits(__floats2half2_rn(oacc[nt][2] * inv1, oacc[nt][3] * inv1));
    }
}

// ---------------------------------------------------------------------------
extern "C" void kernel_launch(void* const* d_in, const int* in_sizes, int n_in,
                              void* d_out, int out_size)
{
    const float* x  = (const float*)d_in[0];
    const float* Wq = (const float*)d_in[1];
    const float* Wk = (const float*)d_in[2];
    const float* Wv = (const float*)d_in[3];
    const float* Wo = (const float*)d_in[4];
    const float* bo = (const float*)d_in[5];
    float* out = (float*)d_out;

    __half *Xb, *Wqb, *Wkb, *Wvb, *Wob, *Qb, *Kb, *Vb, *Cb;
    cudaGetSymbolAddress((void**)&Xb,  g_X);
    cudaGetSymbolAddress((void**)&Wqb, g_Wq);
    cudaGetSymbolAddress((void**)&Wkb, g_Wk);
    cudaGetSymbolAddress((void**)&Wvb, g_Wv);
    cudaGetSymbolAddress((void**)&Wob, g_Wo);
    cudaGetSymbolAddress((void**)&Qb,  g_Q);
    cudaGetSymbolAddress((void**)&Kb,  g_K);
    cudaGetSymbolAddress((void**)&Vb,  g_V);
    cudaGetSymbolAddress((void**)&Cb,  g_ctx);

    const int gsmem = GSTAGES * (A_STG_H + B_STG_H) * 2;
    const int asmem = (128 * QSTRH + 2 * ASTAGES * KV_STG_H) * 2;
    cudaFuncSetAttribute(gemm_f16, cudaFuncAttributeMaxDynamicSharedMemorySize, gsmem);
    cudaFuncSetAttribute(attn_f16, cudaFuncAttributeMaxDynamicSharedMemorySize, asmem);

    // fp32 -> fp16 conversions
    const int n8x = BT * D_MODEL / 8;
    const int n8w = D_MODEL * D_MODEL / 8;
    to_half<<<(n8x + 255) / 256, 256>>>(x,  Xb,  n8x);
    to_half<<<(n8w + 255) / 256, 256>>>(Wq, Wqb, n8w);
    to_half<<<(n8w + 255) / 256, 256>>>(Wk, Wkb, n8w);
    to_half<<<(n8w + 255) / 256, 256>>>(Wv, Wvb, n8w);
    to_half<<<(n8w + 255) / 256, 256>>>(Wo, Wob, n8w);

    // fused QKV projections (Q gets 0.125*log2(e) pre-scale for base-2 softmax)
    dim3 qkvgrid(D_MODEL / 128, BT / 128, 3);   // (8, 32, 3)
    gemm_f16<<<qkvgrid, 256, gsmem>>>(Xb, Wqb, Wkb, Wvb, Qb, Kb, Vb,
                                      nullptr, nullptr, 0, 0.125f * 1.44269504f);

    // attention
    dim3 agrid(SEQ / 128, NHEADS, BATCH);       // (16, 16, 2)
    attn_f16<<<agrid, 256, asmem>>>(Qb, Kb, Vb, Cb);

    // output projection (+bias, fp32 out)
    dim3 ogrid(D_MODEL / 128, BT / 128, 1);
    gemm_f16<<<ogrid, 256, gsmem>>>(Cb, Wob, Wob, Wob, nullptr, nullptr, nullptr,
                                    out, bo, 1, 1.0f);
}

// round 8
// speedup vs baseline: 6.9567x; 1.0899x over previous
#include <cuda_runtime.h>
#include <cuda_fp16.h>
#include <cstdint>

#define D_MODEL 1024
#define NHEADS  16
#define DHEAD   64
#define BATCH   2
#define SEQ     2048
#define BT      (BATCH * SEQ)
#define NQT     (SEQ / 128)     // 16 q-tiles per (b,h)

// Scratch (allocation-free rule: __device__ globals), all fp16
__device__ __half g_X [BT * D_MODEL];
__device__ __half g_Wq[D_MODEL * D_MODEL];
__device__ __half g_Wk[D_MODEL * D_MODEL];
__device__ __half g_Wv[D_MODEL * D_MODEL];
__device__ __half g_Wo[D_MODEL * D_MODEL];
__device__ __half g_Q [BT * D_MODEL];   // pre-scaled by 0.125*log2(e)
__device__ __half g_K [BT * D_MODEL];
__device__ __half g_V [BT * D_MODEL];
__device__ __half g_ctx[BT * D_MODEL];

__device__ __forceinline__ uint32_t h2bits(__half2 h) { return *(uint32_t*)&h; }

__device__ __forceinline__ void mma_f16(float* c, const uint32_t* a, const uint32_t* b) {
    asm volatile(
        "mma.sync.aligned.m16n8k16.row.col.f32.f16.f16.f32 "
        "{%0,%1,%2,%3},{%4,%5,%6,%7},{%8,%9},{%0,%1,%2,%3};"
        : "+f"(c[0]), "+f"(c[1]), "+f"(c[2]), "+f"(c[3])
        : "r"(a[0]), "r"(a[1]), "r"(a[2]), "r"(a[3]), "r"(b[0]), "r"(b[1]));
}

__device__ __forceinline__ void ldsm_x4(uint32_t* r, uint32_t addr) {
    asm volatile("ldmatrix.sync.aligned.m8n8.x4.shared.b16 {%0,%1,%2,%3}, [%4];"
                 : "=r"(r[0]), "=r"(r[1]), "=r"(r[2]), "=r"(r[3]) : "r"(addr));
}
__device__ __forceinline__ void ldsm_x4t(uint32_t* r, uint32_t addr) {
    asm volatile("ldmatrix.sync.aligned.m8n8.x4.trans.shared.b16 {%0,%1,%2,%3}, [%4];"
                 : "=r"(r[0]), "=r"(r[1]), "=r"(r[2]), "=r"(r[3]) : "r"(addr));
}

__device__ __forceinline__ void cp_async16(uint32_t dst_sa, const void* src) {
    asm volatile("cp.async.ca.shared.global [%0], [%1], 16;" :: "r"(dst_sa), "l"(src));
}
__device__ __forceinline__ void cp_commit() { asm volatile("cp.async.commit_group;"); }
__device__ __forceinline__ void cp_wait1()  { asm volatile("cp.async.wait_group 1;" ::: "memory"); }
__device__ __forceinline__ void cp_wait2()  { asm volatile("cp.async.wait_group 2;" ::: "memory"); }

// ---------------------------------------------------------------------------
// fp32 -> fp16 converts
// ---------------------------------------------------------------------------
__global__ __launch_bounds__(256)
void to_half(const float* __restrict__ in, __half* __restrict__ out, int n8)
{
    int i = blockIdx.x * blockDim.x + threadIdx.x;
    if (i < n8) {
        float4 a = ((const float4*)in)[2 * i];
        float4 b = ((const float4*)in)[2 * i + 1];
        uint4 u;
        u.x = h2bits(__floats2half2_rn(a.x, a.y));
        u.y = h2bits(__floats2half2_rn(a.z, a.w));
        u.z = h2bits(__floats2half2_rn(b.x, b.y));
        u.w = h2bits(__floats2half2_rn(b.z, b.w));
        ((uint4*)out)[i] = u;
    }
}

// fused 4-weight conversion: blockIdx.y selects the matrix
__global__ __launch_bounds__(256)
void to_half_w4(const float* __restrict__ w0, const float* __restrict__ w1,
                const float* __restrict__ w2, const float* __restrict__ w3,
                __half* __restrict__ d0, __half* __restrict__ d1,
                __half* __restrict__ d2, __half* __restrict__ d3, int n8)
{
    const int y = blockIdx.y;
    const float* in  = (y == 0) ? w0 : (y == 1) ? w1 : (y == 2) ? w2 : w3;
    __half*      out = (y == 0) ? d0 : (y == 1) ? d1 : (y == 2) ? d2 : d3;
    int i = blockIdx.x * blockDim.x + threadIdx.x;
    if (i < n8) {
        float4 a = ((const float4*)in)[2 * i];
        float4 b = ((const float4*)in)[2 * i + 1];
        uint4 u;
        u.x = h2bits(__floats2half2_rn(a.x, a.y));
        u.y = h2bits(__floats2half2_rn(a.z, a.w));
        u.z = h2bits(__floats2half2_rn(b.x, b.y));
        u.w = h2bits(__floats2half2_rn(b.z, b.w));
        ((uint4*)out)[i] = u;
    }
}

// ---------------------------------------------------------------------------
// fp16 GEMM (verified R4/R6 kernel, unchanged):
// 128x128 CTA tile, BK=32, 4-stage cp.async, 8 warps (4m x 2n), warp 32x64.
// ---------------------------------------------------------------------------
#define ASTRH 40
#define BSTRH 136
#define KTILE 32
#define GSTAGES 4
#define A_STG_H (128 * ASTRH)
#define B_STG_H (KTILE * BSTRH)

__global__ __launch_bounds__(256, 2)
void gemm_f16(const __half* __restrict__ A,
              const __half* __restrict__ B0, const __half* __restrict__ B1,
              const __half* __restrict__ B2,
              __half* __restrict__ H0, __half* __restrict__ H1, __half* __restrict__ H2,
              float* __restrict__ F, const float* __restrict__ bias,
              int fp32_out, float scale0)
{
    extern __shared__ __half smh[];
    __half* As = smh;
    __half* Bs = smh + GSTAGES * A_STG_H;

    const int z = blockIdx.z;
    const __half* B = (z == 0) ? B0 : (z == 1) ? B1 : B2;
    __half*       H = (z == 0) ? H0 : (z == 1) ? H1 : H2;
    const float scale = (z == 0) ? scale0 : 1.0f;

    const int tid  = threadIdx.x;
    const int lane = tid & 31;
    const int wid  = tid >> 5;
    const int wm   = wid & 3;
    const int wn   = wid >> 2;
    const int lr   = lane >> 2;
    const int lc   = lane & 3;
    const int row0 = blockIdx.y * 128;
    const int col0 = blockIdx.x * 128;

    const int arow = tid >> 1;
    const int achk = (tid & 1) * 2;
    const int brow = tid >> 3;
    const int bchk = (tid & 7) * 2;

    const __half* Ag = A + (size_t)(row0 + arow) * D_MODEL + achk * 8;
    const __half* Bg = B + (size_t)brow * D_MODEL + col0 + bchk * 8;
    const uint32_t saA = (uint32_t)__cvta_generic_to_shared(As);
    const uint32_t saB = (uint32_t)__cvta_generic_to_shared(Bs);
    const uint32_t dA0 = saA + (arow * ASTRH + achk * 8) * 2;
    const uint32_t dB0 = saB + (brow * BSTRH + bchk * 8) * 2;

    auto load_tile = [&](int t) {
        int s = t % GSTAGES;
        const __half* a = Ag + t * KTILE;
        const __half* b = Bg + (size_t)t * KTILE * D_MODEL;
        uint32_t da = dA0 + s * A_STG_H * 2;
        uint32_t db = dB0 + s * B_STG_H * 2;
        cp_async16(da,      a);
        cp_async16(da + 16, a + 8);
        cp_async16(db,      b);
        cp_async16(db + 16, b + 8);
    };

    load_tile(0); cp_commit();
    load_tile(1); cp_commit();
    load_tile(2); cp_commit();

    float acc[2][8][4];
#pragma unroll
    for (int mt = 0; mt < 2; mt++)
#pragma unroll
        for (int nt = 0; nt < 8; nt++)
#pragma unroll
            for (int j = 0; j < 4; j++) acc[mt][nt][j] = 0.f;

    const int lrowA = wm * 32 + (lane & 15);
    const int lcolA = (lane >> 4) * 8;
    const int lkB   = (lane & 15);
    const int lnB   = wn * 64 + (lane >> 4) * 8;

    const int kIters = D_MODEL / KTILE;   // 32
    for (int it = 0; it < kIters; ++it) {
        cp_wait2();
        __syncthreads();
        if (it + 3 < kIters) load_tile(it + 3);
        cp_commit();

        const uint32_t bA = saA + (it % GSTAGES) * A_STG_H * 2;
        const uint32_t bB = saB + (it % GSTAGES) * B_STG_H * 2;

#pragma unroll
        for (int kk = 0; kk < 2; ++kk) {
            uint32_t af[2][4];
            ldsm_x4(af[0], bA + ((lrowA) * ASTRH + lcolA + kk * 16) * 2);
            ldsm_x4(af[1], bA + ((lrowA + 16) * ASTRH + lcolA + kk * 16) * 2);
            uint32_t bf[4][4];
#pragma unroll
            for (int ntp = 0; ntp < 4; ntp++)
                ldsm_x4t(bf[ntp], bB + ((lkB + kk * 16) * BSTRH + lnB + ntp * 16) * 2);
#pragma unroll
            for (int mt = 0; mt < 2; mt++)
#pragma unroll
                for (int nt = 0; nt < 8; nt++)
                    mma_f16(acc[mt][nt], af[mt], &bf[nt >> 1][(nt & 1) * 2]);
        }
    }

#pragma unroll
    for (int mt = 0; mt < 2; mt++) {
        int r = row0 + wm * 32 + mt * 16 + lr;
#pragma unroll
        for (int nt = 0; nt < 8; nt++) {
            int c = col0 + wn * 64 + nt * 8 + 2 * lc;
            float* v = acc[mt][nt];
            if (fp32_out) {
                float bx = bias[c], by = bias[c + 1];
                *(float2*)(F + (size_t)r * D_MODEL + c) = make_float2(v[0] + bx, v[1] + by);
                *(float2*)(F + (size_t)(r + 8) * D_MODEL + c) = make_float2(v[2] + bx, v[3] + by);
            } else {
                *(uint32_t*)(H + (size_t)r * D_MODEL + c) =
                    h2bits(__floats2half2_rn(v[0] * scale, v[1] * scale));
                *(uint32_t*)(H + (size_t)(r + 8) * D_MODEL + c) =
                    h2bits(__floats2half2_rn(v[2] * scale, v[3] * scale));
            }
        }
    }
}

// ---------------------------------------------------------------------------
// Causal flash attention, fp16 mma + base-2 online softmax.
// Complementary-pair scheduling: CTA(px,h,b) processes q-tiles {NQT-1-px, px}
// back-to-back -> every CTA does exactly (2*NQT+4)/2 = 36 KV-tile units.
// Grid (NQT/2, H, B) = 256 CTAs = one balanced wave at 2 CTAs/SM.
// ---------------------------------------------------------------------------
#define QSTRH 72
#define KV    64
#define ASTAGES 3
#define KV_STG_H (KV * QSTRH)

__global__ __launch_bounds__(256, 2)
void attn_f16(const __half* __restrict__ Q, const __half* __restrict__ K,
              const __half* __restrict__ V, __half* __restrict__ ctx)
{
    extern __shared__ __half smh[];
    __half* Qs = smh;                         // [128][QSTRH]
    __half* Kd = Qs + 128 * QSTRH;            // [3][KV][QSTRH]
    __half* Vd = Kd + ASTAGES * KV_STG_H;     // [3][KV][QSTRH]

    const int tid  = threadIdx.x;
    const int lane = tid & 31;
    const int wid  = tid >> 5;
    const int lr   = lane >> 2;
    const int lc   = lane & 3;
    const int px   = blockIdx.x;              // 0..NQT/2-1
    const int h    = blockIdx.y;
    const int b    = blockIdx.z;

    const size_t base = (size_t)(b * SEQ) * D_MODEL + h * DHEAD;
    const __half* Kg0 = K + base;
    const __half* Vg0 = V + base;

    const uint32_t saQ = (uint32_t)__cvta_generic_to_shared(Qs);
    const uint32_t saK = (uint32_t)__cvta_generic_to_shared(Kd);
    const uint32_t saV = (uint32_t)__cvta_generic_to_shared(Vd);

    const int krow = tid >> 2;
    const int kchk = (tid & 3) * 2;

    auto copy_kv = [&](int t) {
        int s = t % ASTAGES;
        const __half* Kg = Kg0 + ((size_t)t * KV + krow) * D_MODEL + kchk * 8;
        const __half* Vg = Vg0 + ((size_t)t * KV + krow) * D_MODEL + kchk * 8;
        uint32_t kd = saK + (s * KV_STG_H + krow * QSTRH + kchk * 8) * 2;
        uint32_t vd = saV + (s * KV_STG_H + krow * QSTRH + kchk * 8) * 2;
        cp_async16(kd,      Kg);
        cp_async16(kd + 16, Kg + 8);
        cp_async16(vd,      Vg);
        cp_async16(vd + 16, Vg + 8);
    };

    const int qrow   = wid * 16 + (lane & 15);
    const int qcol   = (lane >> 4) * 8;
    const int krow_f = (lane >> 4) * 8 + (lane & 7);
    const int kcol_f = ((lane >> 3) & 1) * 8;
    const int vrow_f = (lane & 15);
    const int vcol_f = (lane >> 4) * 8;

#pragma unroll 1
    for (int task = 0; task < 2; ++task) {
        const int qt  = task ? px : (NQT - 1 - px);   // heavy first
        const int nkt = 2 * qt + 2;
        const __half* Qg = Q + base + (size_t)qt * 128 * D_MODEL;

        if (task) __syncthreads();   // all warps done with previous task's smem

        // Load Q tile
        for (int i = tid; i < 128 * 8; i += 256) {
            int row = i >> 3, ch = i & 7;
            *(uint4*)&Qs[row * QSTRH + ch * 8] =
                *(const uint4*)(Qg + (size_t)row * D_MODEL + ch * 8);
        }

        copy_kv(0); cp_commit();
        copy_kv(1); cp_commit();

        // Hoist Q fragments (loop-invariant)
        __syncthreads();
        uint32_t qfr[4][4];
#pragma unroll
        for (int kk = 0; kk < 4; kk++)
            ldsm_x4(qfr[kk], saQ + (qrow * QSTRH + qcol + kk * 16) * 2);

        float oacc[8][4];
#pragma unroll
        for (int nt = 0; nt < 8; nt++)
#pragma unroll
            for (int j = 0; j < 4; j++) oacc[nt][j] = 0.f;
        float m0 = -1e30f, m1 = -1e30f, l0 = 0.f, l1 = 0.f;

        const int rg0 = qt * 128 + wid * 16 + lr;

        for (int kt = 0; kt < nkt; ++kt) {
            cp_wait1();
            __syncthreads();
            if (kt + 2 < nkt) copy_kv(kt + 2);
            cp_commit();

            // last diagonal tile: warps 0-3 fully masked -> skip
            if (kt == nkt - 1 && wid < 4) continue;

            const uint32_t bK = saK + (kt % ASTAGES) * KV_STG_H * 2;
            const uint32_t bV = saV + (kt % ASTAGES) * KV_STG_H * 2;

            // S = Q @ K^T : 16 x 64 per warp (log2-unit scores)
            float sacc[8][4];
#pragma unroll
            for (int nt = 0; nt < 8; nt++)
#pragma unroll
                for (int j = 0; j < 4; j++) sacc[nt][j] = 0.f;

#pragma unroll
            for (int kk = 0; kk < 4; ++kk) {
#pragma unroll
                for (int ntp = 0; ntp < 4; ntp++) {
                    uint32_t kf[4];
                    ldsm_x4(kf, bK + ((krow_f + ntp * 16) * QSTRH + kcol_f + kk * 16) * 2);
                    mma_f16(sacc[2 * ntp],     qfr[kk], &kf[0]);
                    mma_f16(sacc[2 * ntp + 1], qfr[kk], &kf[2]);
                }
            }

            // causal mask near the diagonal (last 2 tiles)
            if (kt >= 2 * qt) {
                int cbase = kt * KV;
#pragma unroll
                for (int nt = 0; nt < 8; nt++) {
                    int cg = cbase + nt * 8 + 2 * lc;
                    if (cg     > rg0)     sacc[nt][0] = -1e30f;
                    if (cg + 1 > rg0)     sacc[nt][1] = -1e30f;
                    if (cg     > rg0 + 8) sacc[nt][2] = -1e30f;
                    if (cg + 1 > rg0 + 8) sacc[nt][3] = -1e30f;
                }
            }

            // online softmax (base-2)
            float rm0 = -1e30f, rm1 = -1e30f;
#pragma unroll
            for (int nt = 0; nt < 8; nt++) {
                rm0 = fmaxf(rm0, fmaxf(sacc[nt][0], sacc[nt][1]));
                rm1 = fmaxf(rm1, fmaxf(sacc[nt][2], sacc[nt][3]));
            }
            rm0 = fmaxf(rm0, __shfl_xor_sync(0xffffffffu, rm0, 1));
            rm0 = fmaxf(rm0, __shfl_xor_sync(0xffffffffu, rm0, 2));
            rm1 = fmaxf(rm1, __shfl_xor_sync(0xffffffffu, rm1, 1));
            rm1 = fmaxf(rm1, __shfl_xor_sync(0xffffffffu, rm1, 2));

            float mn0 = fmaxf(m0, rm0), mn1 = fmaxf(m1, rm1);
            float sc0 = exp2f(m0 - mn0), sc1 = exp2f(m1 - mn1);
            float ls0 = 0.f, ls1 = 0.f;
#pragma unroll
            for (int nt = 0; nt < 8; nt++) {
                sacc[nt][0] = exp2f(sacc[nt][0] - mn0);
                sacc[nt][1] = exp2f(sacc[nt][1] - mn0);
                sacc[nt][2] = exp2f(sacc[nt][2] - mn1);
                sacc[nt][3] = exp2f(sacc[nt][3] - mn1);
                ls0 += sacc[nt][0] + sacc[nt][1];
                ls1 += sacc[nt][2] + sacc[nt][3];
            }
            ls0 += __shfl_xor_sync(0xffffffffu, ls0, 1);
            ls0 += __shfl_xor_sync(0xffffffffu, ls0, 2);
            ls1 += __shfl_xor_sync(0xffffffffu, ls1, 1);
            ls1 += __shfl_xor_sync(0xffffffffu, ls1, 2);
            l0 = l0 * sc0 + ls0; m0 = mn0;
            l1 = l1 * sc1 + ls1; m1 = mn1;
#pragma unroll
            for (int nt = 0; nt < 8; nt++) {
                oacc[nt][0] *= sc0; oacc[nt][1] *= sc0;
                oacc[nt][2] *= sc1; oacc[nt][3] *= sc1;
            }

            // O += P @ V
#pragma unroll
            for (int j = 0; j < 4; ++j) {
                uint32_t pf[4];
                pf[0] = h2bits(__floats2half2_rn(sacc[2 * j][0],     sacc[2 * j][1]));
                pf[1] = h2bits(__floats2half2_rn(sacc[2 * j][2],     sacc[2 * j][3]));
                pf[2] = h2bits(__floats2half2_rn(sacc[2 * j + 1][0], sacc[2 * j + 1][1]));
                pf[3] = h2bits(__floats2half2_rn(sacc[2 * j + 1][2], sacc[2 * j + 1][3]));
#pragma unroll
                for (int ntp = 0; ntp < 4; ntp++) {
                    uint32_t vf[4];
                    ldsm_x4t(vf, bV + ((vrow_f + j * 16) * QSTRH + vcol_f + ntp * 16) * 2);
                    mma_f16(oacc[2 * ntp],     pf, &vf[0]);
                    mma_f16(oacc[2 * ntp + 1], pf, &vf[2]);
                }
            }
        }

        // finalize: write fp16 ctx
        float inv0 = 1.f / l0, inv1 = 1.f / l1;
        __half* Cg = ctx + base + (size_t)qt * 128 * D_MODEL;
        int r = wid * 16 + lr;
#pragma unroll
        for (int nt = 0; nt < 8; nt++) {
            int c = nt * 8 + 2 * lc;
            *(uint32_t*)(Cg + (size_t)r * D_MODEL + c) =
                h2bits(__floats2half2_rn(oacc[nt][0] * inv0, oacc[nt][1] * inv0));
            *(uint32_t*)(Cg + (size_t)(r + 8) * D_MODEL + c) =
                h2bits(__floats2half2_rn(oacc[nt][2] * inv1, oacc[nt][3] * inv1));
        }
    }
}

// ---------------------------------------------------------------------------
extern "C" void kernel_launch(void* const* d_in, const int* in_sizes, int n_in,
                              void* d_out, int out_size)
{
    const float* x  = (const float*)d_in[0];
    const float* Wq = (const float*)d_in[1];
    const float* Wk = (const float*)d_in[2];
    const float* Wv = (const float*)d_in[3];
    const float* Wo = (const float*)d_in[4];
    const float* bo = (const float*)d_in[5];
    float* out = (float*)d_out;

    __half *Xb, *Wqb, *Wkb, *Wvb, *Wob, *Qb, *Kb, *Vb, *Cb;
    cudaGetSymbolAddress((void**)&Xb,  g_X);
    cudaGetSymbolAddress((void**)&Wqb, g_Wq);
    cudaGetSymbolAddress((void**)&Wkb, g_Wk);
    cudaGetSymbolAddress((void**)&Wvb, g_Wv);
    cudaGetSymbolAddress((void**)&Wob, g_Wo);
    cudaGetSymbolAddress((void**)&Qb,  g_Q);
    cudaGetSymbolAddress((void**)&Kb,  g_K);
    cudaGetSymbolAddress((void**)&Vb,  g_V);
    cudaGetSymbolAddress((void**)&Cb,  g_ctx);

    const int gsmem = GSTAGES * (A_STG_H + B_STG_H) * 2;
    const int asmem = (128 * QSTRH + 2 * ASTAGES * KV_STG_H) * 2;
    cudaFuncSetAttribute(gemm_f16, cudaFuncAttributeMaxDynamicSharedMemorySize, gsmem);
    cudaFuncSetAttribute(attn_f16, cudaFuncAttributeMaxDynamicSharedMemorySize, asmem);

    // fp32 -> fp16 conversions (x separate; 4 weights in one fused launch)
    const int n8x = BT * D_MODEL / 8;
    const int n8w = D_MODEL * D_MODEL / 8;
    to_half<<<(n8x + 255) / 256, 256>>>(x, Xb, n8x);
    dim3 wgrid((n8w + 255) / 256, 4);
    to_half_w4<<<wgrid, 256>>>(Wq, Wk, Wv, Wo, Wqb, Wkb, Wvb, Wob, n8w);

    // fused QKV projections (Q gets 0.125*log2(e) pre-scale for base-2 softmax)
    dim3 qkvgrid(D_MODEL / 128, BT / 128, 3);   // (8, 32, 3)
    gemm_f16<<<qkvgrid, 256, gsmem>>>(Xb, Wqb, Wkb, Wvb, Qb, Kb, Vb,
                                      nullptr, nullptr, 0, 0.125f * 1.44269504f);

    // attention: complementary-pair balanced grid
    dim3 agrid(NQT / 2, NHEADS, BATCH);         // (8, 16, 2) = 256 CTAs
    attn_f16<<<agrid, 256, asmem>>>(Qb, Kb, Vb, Cb);

    // output projection (+bias, fp32 out)
    dim3 ogrid(D_MODEL / 128, BT / 128, 1);
    gemm_f16<<<ogrid, 256, gsmem>>>(Cb, Wob, Wob, Wob, nullptr, nullptr, nullptr,
                                    out, bo, 1, 1.0f);
}